// round 1
// baseline (speedup 1.0000x reference)
#include <cuda_runtime.h>
#include <stdint.h>

#define R 512
#define K 81
#define IMW_M1 1332.0f
#define IMH_M1 799.0f
#define XCLIP 4.135166556742356f   // log(1000/16)
#define NMS_THRESH 0.5f
#define SCORE_THRESH 0.001f
#define POST_NMS_TOPN 300
#define MAX_PER_IMG 100

// scratch (no allocations allowed)
__device__ float g_boxes[R * K * 4];   // decoded boxes [r][k][4]
__device__ float g_dists[R * K];       // nms_mask * scores

// ---------------------------------------------------------------------------
// Kernel A: bbox_transform
// ---------------------------------------------------------------------------
__global__ void bbox_kernel(const float* __restrict__ rois,
                            const float* __restrict__ deltas) {
    int t = blockIdx.x * blockDim.x + threadIdx.x;
    if (t >= R * K) return;
    int r = t / K;
    int k = t - r * K;

    float x1r = rois[r * 4 + 0];
    float y1r = rois[r * 4 + 1];
    float x2r = rois[r * 4 + 2];
    float y2r = rois[r * 4 + 3];
    float w = x2r - x1r + 1.0f;
    float h = y2r - y1r + 1.0f;
    float cx = x1r + 0.5f * w;
    float cy = y1r + 0.5f * h;

    const float* d = deltas + r * (4 * K) + k * 4;
    float dx = d[0] / 10.0f;
    float dy = d[1] / 10.0f;
    float dw = fminf(d[2] / 5.0f, XCLIP);
    float dh = fminf(d[3] / 5.0f, XCLIP);

    float pcx = dx * w + cx;
    float pcy = dy * h + cy;
    float pw = expf(dw) * w;
    float ph = expf(dh) * h;

    float ox1 = fminf(fmaxf(pcx - 0.5f * pw, 0.0f), IMW_M1);
    float oy1 = fminf(fmaxf(pcy - 0.5f * ph, 0.0f), IMH_M1);
    float ox2 = fminf(fmaxf(pcx + 0.5f * pw - 1.0f, 0.0f), IMW_M1);
    float oy2 = fminf(fmaxf(pcy + 0.5f * ph - 1.0f, 0.0f), IMH_M1);

    float* o = g_boxes + t * 4;
    o[0] = ox1; o[1] = oy1; o[2] = ox2; o[3] = oy2;
}

// ---------------------------------------------------------------------------
// Kernel B: per-class NMS. One block per class, 512 threads.
// ---------------------------------------------------------------------------
__global__ void __launch_bounds__(512, 1) nms_kernel(const float* __restrict__ scores) {
    __shared__ unsigned long long skeys[R];     // (~score_bits)<<32 | idx  (ascending)
    __shared__ float4   sbox[R];
    __shared__ float    sarea[R];
    __shared__ uint32_t smask[R * 16];          // suppression bits, j>i only
    __shared__ uint32_t removed[16];
    __shared__ unsigned char keepf[R];

    const int c = blockIdx.x;
    const int tid = threadIdx.x;

    // pack sort key: descending score, ascending original index (scores > 0)
    float s = scores[tid * K + c];
    uint32_t u = __float_as_uint(s);
    skeys[tid] = (((unsigned long long)(~u)) << 32) | (uint32_t)tid;
    if (tid < 16) removed[tid] = 0u;
    __syncthreads();

    // bitonic sort (ascending keys) — keys unique => deterministic == stable
    for (int k2 = 2; k2 <= R; k2 <<= 1) {
        for (int j = k2 >> 1; j > 0; j >>= 1) {
            int ixj = tid ^ j;
            if (ixj > tid) {
                bool up = ((tid & k2) == 0);
                unsigned long long a = skeys[tid], b = skeys[ixj];
                if ((a > b) == up) { skeys[tid] = b; skeys[ixj] = a; }
            }
            __syncthreads();
        }
    }

    // gather sorted boxes
    int orig = (int)(skeys[tid] & 0xFFFFFFFFull);
    const float* bp = g_boxes + (orig * K + c) * 4;
    float4 b4 = make_float4(bp[0], bp[1], bp[2], bp[3]);
    sbox[tid] = b4;
    float myArea = (b4.z - b4.x + 1.0f) * (b4.w - b4.y + 1.0f);
    sarea[tid] = myArea;
    __syncthreads();

    // suppression bitmask row tid (bits only for j > tid)
    #pragma unroll 1
    for (int w = 0; w < 16; w++) {
        uint32_t m = 0;
        int base = w * 32;
        if (base + 31 > tid) {   // row has no bits <= tid
            #pragma unroll 8
            for (int b = 0; b < 32; b++) {
                int j = base + b;
                if (j > tid) {
                    float4 bb = sbox[j];
                    float xx1 = fmaxf(b4.x, bb.x);
                    float yy1 = fmaxf(b4.y, bb.y);
                    float xx2 = fminf(b4.z, bb.z);
                    float yy2 = fminf(b4.w, bb.w);
                    float iw = fmaxf(xx2 - xx1 + 1.0f, 0.0f);
                    float ih = fmaxf(yy2 - yy1 + 1.0f, 0.0f);
                    float inter = iw * ih;
                    float iou = inter / (myArea + sarea[j] - inter);
                    if (iou > NMS_THRESH) m |= (1u << b);
                }
            }
        }
        smask[tid * 16 + w] = m;
    }
    __syncthreads();

    // warp-serial greedy (cap folded in: capped boxes still suppress)
    if (tid < 32) {
        int kept = 0;
        for (int i = 0; i < R; i++) {
            bool rem = (removed[i >> 5] >> (i & 31)) & 1u;   // uniform across warp
            if (!rem) {
                if (tid == 0) { kept++; keepf[i] = (kept <= POST_NMS_TOPN) ? 1 : 0; }
                if (tid < 16) removed[tid] |= smask[i * 16 + tid];
            } else if (tid == 0) {
                keepf[i] = 0;
            }
            __syncwarp();
        }
    }
    __syncthreads();

    // cls_valid: sorted pos 0 holds the class max score
    float topScore = __uint_as_float(~(uint32_t)(skeys[0] >> 32));
    bool cvalid = (c != 0) && (topScore > SCORE_THRESH);
    float mysc = __uint_as_float(~(uint32_t)(skeys[tid] >> 32));
    g_dists[orig * K + c] = (keepf[tid] && cvalid) ? mysc : 0.0f;
}

// ---------------------------------------------------------------------------
// Kernel C: per-roi max/argmax, global top-100, output assembly.
// ---------------------------------------------------------------------------
__global__ void __launch_bounds__(512, 1) topk_kernel(float* __restrict__ out, int out_size) {
    __shared__ unsigned long long skeys[R];
    __shared__ int slabel[R];
    const int tid = threadIdx.x;

    // zero full output (poisoned by harness)
    for (int i = tid; i < out_size; i += 512) out[i] = 0.0f;

    // per-roi max / first-argmax over K classes (dists >= 0)
    const float* dr = g_dists + tid * K;
    float best = -1.0f; int bl = 0;
    #pragma unroll 1
    for (int k = 0; k < K; k++) {
        float v = dr[k];
        if (v > best) { best = v; bl = k; }
    }
    slabel[tid] = bl;
    uint32_t u = __float_as_uint(best);
    skeys[tid] = (((unsigned long long)(~u)) << 32) | (uint32_t)tid;
    __syncthreads();

    // bitonic sort ascending (score desc, idx asc)
    for (int k2 = 2; k2 <= R; k2 <<= 1) {
        for (int j = k2 >> 1; j > 0; j >>= 1) {
            int ixj = tid ^ j;
            if (ixj > tid) {
                bool up = ((tid & k2) == 0);
                unsigned long long a = skeys[tid], b = skeys[ixj];
                if ((a > b) == up) { skeys[tid] = b; skeys[ixj] = a; }
            }
            __syncthreads();
        }
    }

    if (tid < MAX_PER_IMG) {
        unsigned long long kk = skeys[tid];
        int r = (int)(kk & 0xFFFFFFFFull);
        float s = __uint_as_float(~(uint32_t)(kk >> 32));
        int lbl = slabel[r];
        bool valid = s > SCORE_THRESH;
        const float* bp = g_boxes + (r * K + lbl) * 4;

        // out rows: [score, x1, y1, x2, y2]
        if (out_size >= 5 * MAX_PER_IMG) {
            out[tid * 5 + 0] = valid ? s : 0.0f;
            out[tid * 5 + 1] = valid ? bp[0] : 0.0f;
            out[tid * 5 + 2] = valid ? bp[1] : 0.0f;
            out[tid * 5 + 3] = valid ? bp[2] : 0.0f;
            out[tid * 5 + 4] = valid ? bp[3] : 0.0f;
        }
        // labels_all
        if (out_size >= 6 * MAX_PER_IMG) out[5 * MAX_PER_IMG + tid] = (float)lbl;
        // top
        if (out_size >= 7 * MAX_PER_IMG) out[6 * MAX_PER_IMG + tid] = (float)r;
    }
}

// ---------------------------------------------------------------------------
extern "C" void kernel_launch(void* const* d_in, const int* in_sizes, int n_in,
                              void* d_out, int out_size) {
    const float* rois   = (const float*)d_in[0];
    const float* deltas = (const float*)d_in[1];
    const float* scores = (const float*)d_in[2];
    float* out = (float*)d_out;

    bbox_kernel<<<(R * K + 255) / 256, 256>>>(rois, deltas);
    nms_kernel<<<K, 512>>>(scores);
    topk_kernel<<<1, 512>>>(out, out_size);
}

// round 2
// speedup vs baseline: 3.2340x; 3.2340x over previous
#include <cuda_runtime.h>
#include <stdint.h>

#define R 512
#define K 81
#define IMW_M1 1332.0f
#define IMH_M1 799.0f
#define XCLIP 4.135166556742356f   // log(1000/16)
#define SCORE_THRESH 0.001f
#define POST_NMS_TOPN 300
#define MAX_PER_IMG 100

// scratch (no allocations allowed)
__device__ float g_dists[R * K];       // nms_mask * scores

// ---------------------------------------------------------------------------
// box decode for (roi r, class c), matching reference arithmetic order
// ---------------------------------------------------------------------------
__device__ __forceinline__ float4 decode_box(const float* __restrict__ rois,
                                             const float* __restrict__ deltas,
                                             int r, int c) {
    float4 roi = ((const float4*)rois)[r];
    // deltas row r, class c: byte offset 4*(r*4K + c*4) = r*1296 + c*16 -> 16B aligned
    float4 d = *(const float4*)(deltas + r * (4 * K) + c * 4);

    float w = roi.z - roi.x + 1.0f;
    float h = roi.w - roi.y + 1.0f;
    float cx = roi.x + 0.5f * w;
    float cy = roi.y + 0.5f * h;

    float dx = d.x / 10.0f;
    float dy = d.y / 10.0f;
    float dw = fminf(d.z / 5.0f, XCLIP);
    float dh = fminf(d.w / 5.0f, XCLIP);

    float pcx = dx * w + cx;
    float pcy = dy * h + cy;
    float pw = expf(dw) * w;
    float ph = expf(dh) * h;

    float4 o;
    o.x = fminf(fmaxf(pcx - 0.5f * pw, 0.0f), IMW_M1);
    o.y = fminf(fmaxf(pcy - 0.5f * ph, 0.0f), IMH_M1);
    o.z = fminf(fmaxf(pcx + 0.5f * pw - 1.0f, 0.0f), IMW_M1);
    o.w = fminf(fmaxf(pcy + 0.5f * ph - 1.0f, 0.0f), IMH_M1);
    return o;
}

// ---------------------------------------------------------------------------
// Kernel 1: fused decode + per-class NMS. One block per class, 512 threads.
// ---------------------------------------------------------------------------
__global__ void __launch_bounds__(512, 1)
nms_kernel(const float* __restrict__ rois,
           const float* __restrict__ deltas,
           const float* __restrict__ scores) {
    __shared__ unsigned long long skeys[R];     // (~score_bits)<<32 | idx (asc sort)
    __shared__ float4   sbox[R];                // boxes: by orig idx, then sorted
    __shared__ float    sarea[R];               // areas (sorted order)
    __shared__ uint32_t smask[R * 16];          // suppression bits, j>i only
    __shared__ uint32_t skeep[16];              // final keep bits (sorted order)

    const int c = blockIdx.x;
    const int tid = threadIdx.x;
    const int wid = tid >> 5;
    const int lane = tid & 31;

    // decode my (tid, c) box; stage by original index
    sbox[tid] = decode_box(rois, deltas, tid, c);

    // sort key: descending score, ascending original index (softmax scores > 0)
    float s = scores[tid * K + c];
    skeys[tid] = (((unsigned long long)(~__float_as_uint(s))) << 32) | (uint32_t)tid;

    // zero the full suppression mask
    {
        uint4 z = make_uint4(0, 0, 0, 0);
        uint4* p = (uint4*)(smask + tid * 16);
        p[0] = z; p[1] = z; p[2] = z; p[3] = z;
    }
    __syncthreads();

    // bitonic sort (ascending keys) — keys unique => deterministic stable argsort
    for (int k2 = 2; k2 <= R; k2 <<= 1) {
        for (int j = k2 >> 1; j > 0; j >>= 1) {
            int ixj = tid ^ j;
            if (ixj > tid) {
                bool up = ((tid & k2) == 0);
                unsigned long long a = skeys[tid], b = skeys[ixj];
                if ((a > b) == up) { skeys[tid] = b; skeys[ixj] = a; }
            }
            __syncthreads();
        }
    }

    // permute boxes into sorted order; compute areas (reference expression order)
    int orig = (int)(skeys[tid] & 0xFFFFFFFFull);
    float4 b4 = sbox[orig];
    __syncthreads();
    sbox[tid] = b4;
    sarea[tid] = (b4.z - b4.x + 1.0f) * (b4.w - b4.y + 1.0f);
    __syncthreads();

    // ---- mask build: warp-tiles (32 cols x 32 rows), ballot packing ----
    // tiles with word w >= row-chunk rc (upper triangle incl. diagonal): 136 tiles
    for (int t = wid; t < 136; t += 16) {
        int rc = 0, tt = t;
        while (tt >= 16 - rc) { tt -= 16 - rc; rc++; }
        int w = rc + tt;

        int jcol = (w << 5) + lane;
        float4 cb = sbox[jcol];
        float ca = sarea[jcol];
        int i0 = rc << 5;
        bool diag = (w == rc);

        #pragma unroll 4
        for (int ii = 0; ii < 32; ii++) {
            int i = i0 + ii;
            float4 rb = sbox[i];          // broadcast
            float ra = sarea[i];          // broadcast
            float iw = fminf(cb.z, rb.z) - fmaxf(cb.x, rb.x) + 1.0f;
            float ih = fminf(cb.w, rb.w) - fmaxf(cb.y, rb.y) + 1.0f;
            float inter = fmaxf(iw, 0.0f) * fmaxf(ih, 0.0f);
            // iou > 0.5  <=>  2*inter > union
            bool sup = (inter + inter > (ra + ca) - inter);
            if (diag) sup = sup && (jcol > i);
            uint32_t word = __ballot_sync(0xFFFFFFFFu, sup);
            if (lane == (i & 31)) smask[i * 16 + w] = word;
        }
    }
    __syncthreads();

    // ---- greedy suppression: warp 0, register-resident state ----
    if (wid == 0) {
        uint32_t removedReg = 0;            // lane l (mod 16) owns removed word l
        int kept = 0;
        const int lw = lane & 15;
        uint32_t m_own = smask[0 * 16 + lw];            // row 0 prefetch
        uint32_t mb    = __shfl_sync(0xFFFFFFFFu, m_own, 0);

        for (int ow = 0; ow < 16; ow++) {
            uint32_t cur = __shfl_sync(0xFFFFFFFFu, removedReg, ow);
            uint32_t kcur = 0;
            #pragma unroll
            for (int b = 0; b < 32; b++) {
                int i = (ow << 5) + b;
                uint32_t m = m_own;
                uint32_t mbi = mb;
                // prefetch next row (off the critical chain)
                int inext = (i + 1 < R) ? (i + 1) : i;
                int ownext = (i + 1 < R) ? ((i + 1) >> 5) : ow;
                m_own = smask[inext * 16 + lw];
                mb    = __shfl_sync(0xFFFFFFFFu, m_own, ownext);

                bool rem = (cur >> b) & 1u;
                if (!rem) {
                    kept++;
                    removedReg |= m;
                    cur |= mbi;
                    if (kept <= POST_NMS_TOPN) kcur |= (1u << b);
                }
            }
            if (lane == 0) skeep[ow] = kcur;
        }
    }
    __syncthreads();

    // ---- write dists = keep * cls_valid * score (by original index) ----
    float topScore = __uint_as_float(~(uint32_t)(skeys[0] >> 32));
    bool cvalid = (c != 0) && (topScore > SCORE_THRESH);
    bool kp = (skeep[tid >> 5] >> (tid & 31)) & 1u;
    float mysc = __uint_as_float(~(uint32_t)(skeys[tid] >> 32));
    g_dists[orig * K + c] = (kp && cvalid) ? mysc : 0.0f;
}

// ---------------------------------------------------------------------------
// Kernel 2: per-roi max/argmax, global top-100, output assembly.
// ---------------------------------------------------------------------------
__global__ void __launch_bounds__(512, 1)
topk_kernel(const float* __restrict__ rois,
            const float* __restrict__ deltas,
            float* __restrict__ out, int out_size) {
    __shared__ unsigned long long skeys[R];
    __shared__ int slabel[R];
    const int tid = threadIdx.x;

    // zero full output (poisoned by harness)
    for (int i = tid; i < out_size; i += 512) out[i] = 0.0f;

    // per-roi max / first-argmax over K classes (dists >= 0)
    const float* dr = g_dists + tid * K;
    float best = -1.0f; int bl = 0;
    #pragma unroll 1
    for (int k = 0; k < K; k++) {
        float v = dr[k];
        if (v > best) { best = v; bl = k; }
    }
    slabel[tid] = bl;
    skeys[tid] = (((unsigned long long)(~__float_as_uint(best))) << 32) | (uint32_t)tid;
    __syncthreads();

    // bitonic sort ascending (score desc, idx asc)
    for (int k2 = 2; k2 <= R; k2 <<= 1) {
        for (int j = k2 >> 1; j > 0; j >>= 1) {
            int ixj = tid ^ j;
            if (ixj > tid) {
                bool up = ((tid & k2) == 0);
                unsigned long long a = skeys[tid], b = skeys[ixj];
                if ((a > b) == up) { skeys[tid] = b; skeys[ixj] = a; }
            }
            __syncthreads();
        }
    }

    if (tid < MAX_PER_IMG) {
        unsigned long long kk = skeys[tid];
        int r = (int)(kk & 0xFFFFFFFFull);
        float s = __uint_as_float(~(uint32_t)(kk >> 32));
        int lbl = slabel[r];
        bool valid = s > SCORE_THRESH;
        float4 bb = decode_box(rois, deltas, r, lbl);

        if (out_size >= 5 * MAX_PER_IMG) {
            out[tid * 5 + 0] = valid ? s : 0.0f;
            out[tid * 5 + 1] = valid ? bb.x : 0.0f;
            out[tid * 5 + 2] = valid ? bb.y : 0.0f;
            out[tid * 5 + 3] = valid ? bb.z : 0.0f;
            out[tid * 5 + 4] = valid ? bb.w : 0.0f;
        }
        if (out_size >= 6 * MAX_PER_IMG) out[5 * MAX_PER_IMG + tid] = (float)lbl;
        if (out_size >= 7 * MAX_PER_IMG) out[6 * MAX_PER_IMG + tid] = (float)r;
    }
}

// ---------------------------------------------------------------------------
extern "C" void kernel_launch(void* const* d_in, const int* in_sizes, int n_in,
                              void* d_out, int out_size) {
    const float* rois   = (const float*)d_in[0];
    const float* deltas = (const float*)d_in[1];
    const float* scores = (const float*)d_in[2];
    float* out = (float*)d_out;

    nms_kernel<<<K, 512>>>(rois, deltas, scores);
    topk_kernel<<<1, 512>>>(rois, deltas, out, out_size);
}

// round 3
// speedup vs baseline: 3.2419x; 1.0025x over previous
#include <cuda_runtime.h>
#include <stdint.h>

#define R 512
#define K 81
#define IMW_M1 1332.0f
#define IMH_M1 799.0f
#define XCLIP 4.135166556742356f   // log(1000/16)
#define SCORE_THRESH 0.001f
#define POST_NMS_TOPN 300
#define MAX_PER_IMG 100

// scratch (no allocations allowed)
__device__ float g_dists[K * R];        // column-major: [class][roi]
__device__ unsigned int g_sync;         // threadfence-reduction counter (self-resetting)

// ---------------------------------------------------------------------------
// box decode for (roi r, class c), matching reference arithmetic order
// ---------------------------------------------------------------------------
__device__ __forceinline__ float4 decode_box(const float* __restrict__ rois,
                                             const float* __restrict__ deltas,
                                             int r, int c) {
    float4 roi = ((const float4*)rois)[r];
    float4 d = *(const float4*)(deltas + r * (4 * K) + c * 4);   // 16B aligned

    float w = roi.z - roi.x + 1.0f;
    float h = roi.w - roi.y + 1.0f;
    float cx = roi.x + 0.5f * w;
    float cy = roi.y + 0.5f * h;

    float dx = d.x / 10.0f;
    float dy = d.y / 10.0f;
    float dw = fminf(d.z / 5.0f, XCLIP);
    float dh = fminf(d.w / 5.0f, XCLIP);

    float pcx = dx * w + cx;
    float pcy = dy * h + cy;
    float pw = expf(dw) * w;
    float ph = expf(dh) * h;

    float4 o;
    o.x = fminf(fmaxf(pcx - 0.5f * pw, 0.0f), IMW_M1);
    o.y = fminf(fmaxf(pcy - 0.5f * ph, 0.0f), IMH_M1);
    o.z = fminf(fmaxf(pcx + 0.5f * pw - 1.0f, 0.0f), IMW_M1);
    o.w = fminf(fmaxf(pcy + 0.5f * ph - 1.0f, 0.0f), IMH_M1);
    return o;
}

// ---------------------------------------------------------------------------
// Single fused kernel: decode + per-class NMS (one block per class) + final
// top-100 assembly done by the last block to finish (threadfence reduction).
// ---------------------------------------------------------------------------
__global__ void __launch_bounds__(512, 1)
fused_kernel(const float* __restrict__ rois,
             const float* __restrict__ deltas,
             const float* __restrict__ scores,
             float* __restrict__ out, int out_size) {
    __shared__ unsigned long long skeys[R];     // (~score_bits)<<32 | idx (asc sort)
    __shared__ float4   sbox[R];
    __shared__ float    sarea[R];
    __shared__ uint32_t smask[R * 16];          // suppression bits, j>i only
    __shared__ uint32_t skeep[16];
    __shared__ int      sIsLast;

    const int c = blockIdx.x;
    const int tid = threadIdx.x;
    const int wid = tid >> 5;
    const int lane = tid & 31;

    // decode my (tid, c) box; stage by original index
    sbox[tid] = decode_box(rois, deltas, tid, c);

    // sort key: descending score, ascending original index (softmax scores > 0)
    float s = scores[tid * K + c];
    skeys[tid] = (((unsigned long long)(~__float_as_uint(s))) << 32) | (uint32_t)tid;

    // zero my suppression-mask row
    {
        uint4 z = make_uint4(0, 0, 0, 0);
        uint4* p = (uint4*)(smask + tid * 16);
        p[0] = z; p[1] = z; p[2] = z; p[3] = z;
    }
    __syncthreads();

    // bitonic sort (ascending keys) — unique keys => deterministic stable argsort
    for (int k2 = 2; k2 <= R; k2 <<= 1) {
        for (int j = k2 >> 1; j > 0; j >>= 1) {
            int ixj = tid ^ j;
            if (ixj > tid) {
                bool up = ((tid & k2) == 0);
                unsigned long long a = skeys[tid], b = skeys[ixj];
                if ((a > b) == up) { skeys[tid] = b; skeys[ixj] = a; }
            }
            __syncthreads();
        }
    }

    // permute boxes into sorted order; areas in reference expression order
    int orig = (int)(skeys[tid] & 0xFFFFFFFFull);
    float4 b4 = sbox[orig];
    __syncthreads();
    sbox[tid] = b4;
    sarea[tid] = (b4.z - b4.x + 1.0f) * (b4.w - b4.y + 1.0f);
    __syncthreads();

    // ---- mask build: warp tiles (32 cols x 32 rows), ballot packing ----
    for (int t = wid; t < 136; t += 16) {
        int rc = 0, tt = t;
        while (tt >= 16 - rc) { tt -= 16 - rc; rc++; }
        int w = rc + tt;

        int jcol = (w << 5) + lane;
        float4 cb = sbox[jcol];
        float ca = sarea[jcol];
        int i0 = rc << 5;
        bool diag = (w == rc);

        #pragma unroll 4
        for (int ii = 0; ii < 32; ii++) {
            int i = i0 + ii;
            float4 rb = sbox[i];
            float ra = sarea[i];
            float iw = fminf(cb.z, rb.z) - fmaxf(cb.x, rb.x) + 1.0f;
            float ih = fminf(cb.w, rb.w) - fmaxf(cb.y, rb.y) + 1.0f;
            float inter = fmaxf(iw, 0.0f) * fmaxf(ih, 0.0f);
            bool sup = (inter + inter > (ra + ca) - inter);   // iou > 0.5
            if (diag) sup = sup && (jcol > i);
            uint32_t word = __ballot_sync(0xFFFFFFFFu, sup);
            if (lane == (i & 31)) smask[i * 16 + w] = word;
        }
    }
    __syncthreads();

    // ---- greedy suppression: warp 0, register-resident state ----
    if (wid == 0) {
        uint32_t removedReg = 0;
        int kept = 0;
        const int lw = lane & 15;
        uint32_t m_own = smask[0 * 16 + lw];
        uint32_t mb    = __shfl_sync(0xFFFFFFFFu, m_own, 0);

        for (int ow = 0; ow < 16; ow++) {
            uint32_t cur = __shfl_sync(0xFFFFFFFFu, removedReg, ow);
            uint32_t kcur = 0;
            #pragma unroll
            for (int b = 0; b < 32; b++) {
                int i = (ow << 5) + b;
                uint32_t m = m_own;
                uint32_t mbi = mb;
                int inext = (i + 1 < R) ? (i + 1) : i;
                int ownext = (i + 1 < R) ? ((i + 1) >> 5) : ow;
                m_own = smask[inext * 16 + lw];
                mb    = __shfl_sync(0xFFFFFFFFu, m_own, ownext);

                bool rem = (cur >> b) & 1u;
                if (!rem) {
                    kept++;
                    removedReg |= m;
                    cur |= mbi;
                    if (kept <= POST_NMS_TOPN) kcur |= (1u << b);
                }
            }
            if (lane == 0) skeep[ow] = kcur;
        }
    }
    __syncthreads();

    // ---- write dists column (column-major for coalesced tail reads) ----
    float topScore = __uint_as_float(~(uint32_t)(skeys[0] >> 32));
    bool cvalid = (c != 0) && (topScore > SCORE_THRESH);
    bool kp = (skeep[tid >> 5] >> (tid & 31)) & 1u;
    float mysc = __uint_as_float(~(uint32_t)(skeys[tid] >> 32));
    g_dists[c * R + orig] = (kp && cvalid) ? mysc : 0.0f;

    // ---- threadfence reduction: last block runs the top-100 tail ----
    __threadfence();
    __syncthreads();
    if (tid == 0) {
        unsigned int done = atomicAdd(&g_sync, 1u);
        sIsLast = (done == K - 1) ? 1 : 0;
        if (sIsLast) g_sync = 0;   // reset for next graph replay
    }
    __syncthreads();
    if (!sIsLast) return;
    __threadfence();

    // ================= tail: per-roi argmax + top-100 =================
    int* slabel = (int*)smask;      // reuse shared

    // zero full output (poisoned by harness)
    for (int i = tid; i < out_size; i += 512) out[i] = 0.0f;

    // per-roi max / first-argmax over K classes — coalesced column loads
    float best = -1.0f; int bl = 0;
    #pragma unroll 1
    for (int cc = 0; cc < K; cc++) {
        float v = __ldcg(&g_dists[cc * R + tid]);
        if (v > best) { best = v; bl = cc; }
    }
    slabel[tid] = bl;
    skeys[tid] = (((unsigned long long)(~__float_as_uint(best))) << 32) | (uint32_t)tid;
    __syncthreads();

    // bitonic sort ascending (score desc, idx asc)
    for (int k2 = 2; k2 <= R; k2 <<= 1) {
        for (int j = k2 >> 1; j > 0; j >>= 1) {
            int ixj = tid ^ j;
            if (ixj > tid) {
                bool up = ((tid & k2) == 0);
                unsigned long long a = skeys[tid], b = skeys[ixj];
                if ((a > b) == up) { skeys[tid] = b; skeys[ixj] = a; }
            }
            __syncthreads();
        }
    }

    if (tid < MAX_PER_IMG) {
        unsigned long long kk = skeys[tid];
        int r = (int)(kk & 0xFFFFFFFFull);
        float sc = __uint_as_float(~(uint32_t)(kk >> 32));
        int lbl = slabel[r];
        bool valid = sc > SCORE_THRESH;
        float4 bb = decode_box(rois, deltas, r, lbl);

        if (out_size >= 5 * MAX_PER_IMG) {
            out[tid * 5 + 0] = valid ? sc : 0.0f;
            out[tid * 5 + 1] = valid ? bb.x : 0.0f;
            out[tid * 5 + 2] = valid ? bb.y : 0.0f;
            out[tid * 5 + 3] = valid ? bb.z : 0.0f;
            out[tid * 5 + 4] = valid ? bb.w : 0.0f;
        }
        if (out_size >= 6 * MAX_PER_IMG) out[5 * MAX_PER_IMG + tid] = (float)lbl;
        if (out_size >= 7 * MAX_PER_IMG) out[6 * MAX_PER_IMG + tid] = (float)r;
    }
}

// ---------------------------------------------------------------------------
extern "C" void kernel_launch(void* const* d_in, const int* in_sizes, int n_in,
                              void* d_out, int out_size) {
    const float* rois   = (const float*)d_in[0];
    const float* deltas = (const float*)d_in[1];
    const float* scores = (const float*)d_in[2];
    float* out = (float*)d_out;

    fused_kernel<<<K, 512>>>(rois, deltas, scores, out, out_size);
}

// round 4
// speedup vs baseline: 3.2903x; 1.0149x over previous
#include <cuda_runtime.h>
#include <stdint.h>

#define R 512
#define K 81
#define IMW_M1 1332.0f
#define IMH_M1 799.0f
#define XCLIP 4.135166556742356f   // log(1000/16)
#define SCORE_THRESH 0.001f
#define POST_NMS_TOPN 300
#define MAX_PER_IMG 100

// scratch (no allocations allowed)
__device__ unsigned long long g_rmax[R];   // per-roi packed (score_bits<<32 | 255-class)
__device__ unsigned int g_sync;            // threadfence-reduction counter (self-reset)

// ---------------------------------------------------------------------------
// box decode for (roi r, class c), matching reference arithmetic order
// ---------------------------------------------------------------------------
__device__ __forceinline__ float4 decode_box(const float* __restrict__ rois,
                                             const float* __restrict__ deltas,
                                             int r, int c) {
    float4 roi = ((const float4*)rois)[r];
    float4 d = *(const float4*)(deltas + r * (4 * K) + c * 4);   // 16B aligned

    float w = roi.z - roi.x + 1.0f;
    float h = roi.w - roi.y + 1.0f;
    float cx = roi.x + 0.5f * w;
    float cy = roi.y + 0.5f * h;

    float dx = d.x / 10.0f;
    float dy = d.y / 10.0f;
    float dw = fminf(d.z / 5.0f, XCLIP);
    float dh = fminf(d.w / 5.0f, XCLIP);

    float pcx = dx * w + cx;
    float pcy = dy * h + cy;
    float pw = expf(dw) * w;
    float ph = expf(dh) * h;

    float4 o;
    o.x = fminf(fmaxf(pcx - 0.5f * pw, 0.0f), IMW_M1);
    o.y = fminf(fmaxf(pcy - 0.5f * ph, 0.0f), IMH_M1);
    o.z = fminf(fmaxf(pcx + 0.5f * pw - 1.0f, 0.0f), IMW_M1);
    o.w = fminf(fmaxf(pcy + 0.5f * ph - 1.0f, 0.0f), IMH_M1);
    return o;
}

// ---------------------------------------------------------------------------
// Single-warp register bitonic sort of 512 u64 keys (ascending), no barriers.
// Element e = lane*16 + r  (bits 0-3 = r, bits 4-8 = lane).
// Canonical XOR bitonic: up = ((e & k2)==0); swap-if ((a[e]>a[p])==up), p=e^j>e.
// ---------------------------------------------------------------------------
__device__ __forceinline__ void warp_sort512(unsigned long long* skeys, int lane) {
    unsigned long long k[16];
    #pragma unroll
    for (int r = 0; r < 16; r++) k[r] = skeys[lane * 16 + r];

    #pragma unroll
    for (int k2 = 2; k2 <= 512; k2 <<= 1) {
        #pragma unroll
        for (int j = k2 >> 1; j > 0; j >>= 1) {
            if (j >= 16) {
                // cross-lane: partner lane = lane ^ (j>>4); k2 >= 32 here
                int jl = j >> 4;
                bool amHigh = (lane & jl) != 0;
                bool up = ((lane & (k2 >> 4)) == 0);
                bool takeMax = (up == amHigh);
                #pragma unroll
                for (int r = 0; r < 16; r++) {
                    unsigned long long pk = __shfl_xor_sync(0xFFFFFFFFu, k[r], jl);
                    unsigned long long mx = (k[r] > pk) ? k[r] : pk;
                    unsigned long long mn = (k[r] > pk) ? pk : k[r];
                    k[r] = takeMax ? mx : mn;
                }
            } else {
                // intra-lane: partner r^j
                #pragma unroll
                for (int r = 0; r < 16; r++) {
                    int rp = r ^ j;
                    if (rp > r) {
                        bool up = (k2 < 16) ? ((r & k2) == 0)
                                            : ((lane & (k2 >> 4)) == 0);
                        if ((k[r] > k[rp]) == up) {
                            unsigned long long t = k[r]; k[r] = k[rp]; k[rp] = t;
                        }
                    }
                }
            }
        }
    }
    #pragma unroll
    for (int r = 0; r < 16; r++) skeys[lane * 16 + r] = k[r];
}

// ---------------------------------------------------------------------------
// Fused kernel: decode + per-class NMS (one block/class) + last-block top-100.
// ---------------------------------------------------------------------------
__global__ void __launch_bounds__(512, 1)
fused_kernel(const float* __restrict__ rois,
             const float* __restrict__ deltas,
             const float* __restrict__ scores,
             float* __restrict__ out, int out_size) {
    __shared__ unsigned long long skeys[R];     // (~score_bits)<<32 | idx
    __shared__ float4   sbox[R];
    __shared__ float    sarea[R];
    __shared__ uint32_t smask[R * 16];          // suppression bits, j>i only
    __shared__ uint32_t skeep[16];
    __shared__ int      sIsLast;

    const int c = blockIdx.x;
    const int tid = threadIdx.x;
    const int wid = tid >> 5;
    const int lane = tid & 31;

    // decode my (tid, c) box; stage by original index
    sbox[tid] = decode_box(rois, deltas, tid, c);

    // sort key: descending score, ascending original index (softmax scores > 0)
    float s = scores[tid * K + c];
    skeys[tid] = (((unsigned long long)(~__float_as_uint(s))) << 32) | (uint32_t)tid;

    // zero my suppression-mask row
    {
        uint4 z = make_uint4(0, 0, 0, 0);
        uint4* p = (uint4*)(smask + tid * 16);
        p[0] = z; p[1] = z; p[2] = z; p[3] = z;
    }
    __syncthreads();

    // single-warp register sort (no barriers inside)
    if (wid == 0) warp_sort512(skeys, lane);
    __syncthreads();

    // permute boxes into sorted order; areas in reference expression order
    int orig = (int)(skeys[tid] & 0xFFFFFFFFull);
    float4 b4 = sbox[orig];
    __syncthreads();
    sbox[tid] = b4;
    sarea[tid] = (b4.z - b4.x + 1.0f) * (b4.w - b4.y + 1.0f);
    __syncthreads();

    // ---- mask build: warp tiles (32 cols x 32 rows), ballot packing ----
    for (int t = wid; t < 136; t += 16) {
        int rc = 0, tt = t;
        while (tt >= 16 - rc) { tt -= 16 - rc; rc++; }
        int w = rc + tt;

        int jcol = (w << 5) + lane;
        float4 cb = sbox[jcol];
        float ca = sarea[jcol];
        int i0 = rc << 5;
        bool diag = (w == rc);

        #pragma unroll 4
        for (int ii = 0; ii < 32; ii++) {
            int i = i0 + ii;
            float4 rb = sbox[i];
            float ra = sarea[i];
            float iw = fminf(cb.z, rb.z) - fmaxf(cb.x, rb.x) + 1.0f;
            float ih = fminf(cb.w, rb.w) - fmaxf(cb.y, rb.y) + 1.0f;
            float inter = fmaxf(iw, 0.0f) * fmaxf(ih, 0.0f);
            bool sup = (inter + inter > (ra + ca) - inter);   // iou > 0.5
            if (diag) sup = sup && (jcol > i);
            uint32_t word = __ballot_sync(0xFFFFFFFFu, sup);
            if (lane == (i & 31)) smask[i * 16 + w] = word;
        }
    }
    __syncthreads();

    // ---- greedy suppression: warp 0, lane-replicated current word ----
    if (wid == 0) {
        uint32_t remw = 0;              // lane l (&15) owns removed word l&15
        const int lw = lane & 15;
        int kept = 0;
        #pragma unroll 1
        for (int ow = 0; ow < 16; ow++) {
            uint32_t cur = __shfl_sync(0xFFFFFFFFu, remw, ow);
            // hoistable broadcast preload of this word-block's own words
            uint32_t mo[32];
            #pragma unroll
            for (int b = 0; b < 32; b++) mo[b] = smask[(ow * 32 + b) * 16 + ow];
            uint32_t kcur = 0;
            #pragma unroll
            for (int b = 0; b < 32; b++) {
                uint32_t ml = smask[(ow * 32 + b) * 16 + lw];
                if (!((cur >> b) & 1u)) {      // uniform: cur replicated
                    kept++;
                    cur  |= mo[b];
                    remw |= ml;
                    if (kept <= POST_NMS_TOPN) kcur |= (1u << b);
                }
            }
            if (lane == 0) skeep[ow] = kcur;
        }
    }
    __syncthreads();

    // ---- per-roi class-max via packed atomicMax (replaces dists+argmax) ----
    float topScore = __uint_as_float(~(uint32_t)(skeys[0] >> 32));
    bool cvalid = (c != 0) && (topScore > SCORE_THRESH);
    bool kp = (skeep[tid >> 5] >> (tid & 31)) & 1u;
    if (kp && cvalid) {
        uint32_t bits = ~(uint32_t)(skeys[tid] >> 32);   // score float bits (>0)
        unsigned long long key =
            (((unsigned long long)bits) << 32) | (unsigned int)(255 - c);
        atomicMax(&g_rmax[orig], key);
    }

    // ---- threadfence reduction: last block runs the top-100 tail ----
    __threadfence();
    __syncthreads();
    if (tid == 0) {
        unsigned int done = atomicAdd(&g_sync, 1u);
        sIsLast = (done == K - 1) ? 1 : 0;
        if (done == K - 1) g_sync = 0;   // reset for next graph replay
    }
    __syncthreads();
    if (!sIsLast) return;

    // ================= tail: top-100 assembly =================
    int* slabel = (int*)smask;          // reuse shared

    // zero full output (poisoned by harness)
    for (int i = tid; i < out_size; i += 512) out[i] = 0.0f;

    // coherent read + self-reset in one atomic
    unsigned long long v = atomicExch(&g_rmax[tid], 0ull);
    uint32_t bits = (uint32_t)(v >> 32);            // 0 if nothing kept
    int lbl = (v != 0ull) ? (255 - (int)(v & 0xFFull)) : 0;
    slabel[tid] = lbl;
    skeys[tid] = (((unsigned long long)(~bits)) << 32) | (uint32_t)tid;
    __syncthreads();

    if (wid == 0) warp_sort512(skeys, lane);
    __syncthreads();

    if (tid < MAX_PER_IMG) {
        unsigned long long kk = skeys[tid];
        int r = (int)(kk & 0xFFFFFFFFull);
        float sc = __uint_as_float(~(uint32_t)(kk >> 32));
        int lbl2 = slabel[r];
        bool valid = sc > SCORE_THRESH;
        float4 bb = decode_box(rois, deltas, r, lbl2);

        if (out_size >= 5 * MAX_PER_IMG) {
            out[tid * 5 + 0] = valid ? sc : 0.0f;
            out[tid * 5 + 1] = valid ? bb.x : 0.0f;
            out[tid * 5 + 2] = valid ? bb.y : 0.0f;
            out[tid * 5 + 3] = valid ? bb.z : 0.0f;
            out[tid * 5 + 4] = valid ? bb.w : 0.0f;
        }
        if (out_size >= 6 * MAX_PER_IMG) out[5 * MAX_PER_IMG + tid] = (float)lbl2;
        if (out_size >= 7 * MAX_PER_IMG) out[6 * MAX_PER_IMG + tid] = (float)r;
    }
}

// ---------------------------------------------------------------------------
extern "C" void kernel_launch(void* const* d_in, const int* in_sizes, int n_in,
                              void* d_out, int out_size) {
    const float* rois   = (const float*)d_in[0];
    const float* deltas = (const float*)d_in[1];
    const float* scores = (const float*)d_in[2];
    float* out = (float*)d_out;

    fused_kernel<<<K, 512>>>(rois, deltas, scores, out, out_size);
}

// round 5
// speedup vs baseline: 4.0834x; 1.2410x over previous
#include <cuda_runtime.h>
#include <stdint.h>

#define R 512
#define K 81
#define IMW_M1 1332.0f
#define IMH_M1 799.0f
#define XCLIP 4.135166556742356f   // log(1000/16)
#define SCORE_THRESH 0.001f
#define POST_NMS_TOPN 300
#define MAX_PER_IMG 100

// scratch (no allocations allowed)
__device__ unsigned long long g_rmax[R];   // per-roi packed (score_bits<<32 | 255-class)
__device__ unsigned int g_sync;            // threadfence-reduction counter (self-reset)

// ---------------------------------------------------------------------------
// box decode for (roi r, class c), matching reference arithmetic order
// ---------------------------------------------------------------------------
__device__ __forceinline__ float4 decode_box(const float* __restrict__ rois,
                                             const float* __restrict__ deltas,
                                             int r, int c) {
    float4 roi = ((const float4*)rois)[r];
    float4 d = *(const float4*)(deltas + r * (4 * K) + c * 4);   // 16B aligned

    float w = roi.z - roi.x + 1.0f;
    float h = roi.w - roi.y + 1.0f;
    float cx = roi.x + 0.5f * w;
    float cy = roi.y + 0.5f * h;

    float dx = d.x / 10.0f;
    float dy = d.y / 10.0f;
    float dw = fminf(d.z / 5.0f, XCLIP);
    float dh = fminf(d.w / 5.0f, XCLIP);

    float pcx = dx * w + cx;
    float pcy = dy * h + cy;
    float pw = expf(dw) * w;
    float ph = expf(dh) * h;

    float4 o;
    o.x = fminf(fmaxf(pcx - 0.5f * pw, 0.0f), IMW_M1);
    o.y = fminf(fmaxf(pcy - 0.5f * ph, 0.0f), IMH_M1);
    o.z = fminf(fmaxf(pcx + 0.5f * pw - 1.0f, 0.0f), IMW_M1);
    o.w = fminf(fmaxf(pcy + 0.5f * ph - 1.0f, 0.0f), IMH_M1);
    return o;
}

// ---------------------------------------------------------------------------
// Fused kernel: decode + per-class NMS (one block/class) + last-block top-100.
// Sorts: 16-warp shared-memory bitonic (all threads work — measured fastest).
// ---------------------------------------------------------------------------
__global__ void __launch_bounds__(512, 1)
fused_kernel(const float* __restrict__ rois,
             const float* __restrict__ deltas,
             const float* __restrict__ scores,
             float* __restrict__ out, int out_size) {
    __shared__ unsigned long long skeys[R];     // (~score_bits)<<32 | idx (asc sort)
    __shared__ float4   sbox[R];
    __shared__ float    sarea[R];
    __shared__ uint32_t smask[R * 16];          // suppression bits, j>i only
    __shared__ uint32_t skeep[16];
    __shared__ int      sIsLast;

    const int c = blockIdx.x;
    const int tid = threadIdx.x;
    const int wid = tid >> 5;
    const int lane = tid & 31;

    // decode my (tid, c) box; stage by original index
    sbox[tid] = decode_box(rois, deltas, tid, c);

    // sort key: descending score, ascending original index (softmax scores > 0)
    float s = scores[tid * K + c];
    skeys[tid] = (((unsigned long long)(~__float_as_uint(s))) << 32) | (uint32_t)tid;

    // zero my suppression-mask row
    {
        uint4 z = make_uint4(0, 0, 0, 0);
        uint4* p = (uint4*)(smask + tid * 16);
        p[0] = z; p[1] = z; p[2] = z; p[3] = z;
    }
    __syncthreads();

    // 16-warp shared-memory bitonic sort (ascending; unique keys => stable argsort)
    for (int k2 = 2; k2 <= R; k2 <<= 1) {
        for (int j = k2 >> 1; j > 0; j >>= 1) {
            int ixj = tid ^ j;
            if (ixj > tid) {
                bool up = ((tid & k2) == 0);
                unsigned long long a = skeys[tid], b = skeys[ixj];
                if ((a > b) == up) { skeys[tid] = b; skeys[ixj] = a; }
            }
            __syncthreads();
        }
    }

    // permute boxes into sorted order; areas in reference expression order
    int orig = (int)(skeys[tid] & 0xFFFFFFFFull);
    float4 b4 = sbox[orig];
    __syncthreads();
    sbox[tid] = b4;
    sarea[tid] = (b4.z - b4.x + 1.0f) * (b4.w - b4.y + 1.0f);
    __syncthreads();

    // ---- mask build: warp tiles (32 cols x 32 rows), ballot packing ----
    for (int t = wid; t < 136; t += 16) {
        int rc = 0, tt = t;
        while (tt >= 16 - rc) { tt -= 16 - rc; rc++; }
        int w = rc + tt;

        int jcol = (w << 5) + lane;
        float4 cb = sbox[jcol];
        float ca = sarea[jcol];
        int i0 = rc << 5;
        bool diag = (w == rc);

        #pragma unroll 4
        for (int ii = 0; ii < 32; ii++) {
            int i = i0 + ii;
            float4 rb = sbox[i];
            float ra = sarea[i];
            float iw = fminf(cb.z, rb.z) - fmaxf(cb.x, rb.x) + 1.0f;
            float ih = fminf(cb.w, rb.w) - fmaxf(cb.y, rb.y) + 1.0f;
            float inter = fmaxf(iw, 0.0f) * fmaxf(ih, 0.0f);
            bool sup = (inter + inter > (ra + ca) - inter);   // iou > 0.5
            if (diag) sup = sup && (jcol > i);
            uint32_t word = __ballot_sync(0xFFFFFFFFu, sup);
            if (lane == (i & 31)) smask[i * 16 + w] = word;
        }
    }
    __syncthreads();

    // ---- greedy suppression: warp 0, lane-replicated current word ----
    if (wid == 0) {
        uint32_t remw = 0;              // lane l (&15) owns removed word l&15
        const int lw = lane & 15;
        int kept = 0;
        #pragma unroll 1
        for (int ow = 0; ow < 16; ow++) {
            uint32_t cur = __shfl_sync(0xFFFFFFFFu, remw, ow);
            // preload this word-block's own suppression words (broadcast LDS)
            uint32_t mo[32];
            #pragma unroll
            for (int b = 0; b < 32; b++) mo[b] = smask[(ow * 32 + b) * 16 + ow];
            uint32_t kcur = 0;
            #pragma unroll
            for (int b = 0; b < 32; b++) {
                uint32_t ml = smask[(ow * 32 + b) * 16 + lw];
                if (!((cur >> b) & 1u)) {      // uniform: cur replicated in all lanes
                    kept++;
                    cur  |= mo[b];
                    remw |= ml;
                    if (kept <= POST_NMS_TOPN) kcur |= (1u << b);
                }
            }
            if (lane == 0) skeep[ow] = kcur;
        }
    }
    __syncthreads();

    // ---- per-roi class-max via packed atomicMax ----
    float topScore = __uint_as_float(~(uint32_t)(skeys[0] >> 32));
    bool cvalid = (c != 0) && (topScore > SCORE_THRESH);
    bool kp = (skeep[tid >> 5] >> (tid & 31)) & 1u;
    if (kp && cvalid) {
        uint32_t bits = ~(uint32_t)(skeys[tid] >> 32);   // score float bits (>0)
        unsigned long long key =
            (((unsigned long long)bits) << 32) | (unsigned int)(255 - c);
        atomicMax(&g_rmax[orig], key);
    }

    // ---- threadfence reduction: last block runs the top-100 tail ----
    __threadfence();
    __syncthreads();
    if (tid == 0) {
        unsigned int done = atomicAdd(&g_sync, 1u);
        sIsLast = (done == K - 1) ? 1 : 0;
        if (done == K - 1) g_sync = 0;   // reset for next graph replay
    }
    __syncthreads();
    if (!sIsLast) return;

    // ================= tail: top-100 assembly =================
    int* slabel = (int*)smask;          // reuse shared

    // zero full output (poisoned by harness)
    for (int i = tid; i < out_size; i += 512) out[i] = 0.0f;

    // coherent read + self-reset in one atomic
    unsigned long long v = atomicExch(&g_rmax[tid], 0ull);
    uint32_t bits = (uint32_t)(v >> 32);            // 0 if nothing kept
    int lbl = (v != 0ull) ? (255 - (int)(v & 0xFFull)) : 0;
    slabel[tid] = lbl;
    skeys[tid] = (((unsigned long long)(~bits)) << 32) | (uint32_t)tid;
    __syncthreads();

    // 16-warp shared-memory bitonic sort (score desc, idx asc)
    for (int k2 = 2; k2 <= R; k2 <<= 1) {
        for (int j = k2 >> 1; j > 0; j >>= 1) {
            int ixj = tid ^ j;
            if (ixj > tid) {
                bool up = ((tid & k2) == 0);
                unsigned long long a = skeys[tid], b = skeys[ixj];
                if ((a > b) == up) { skeys[tid] = b; skeys[ixj] = a; }
            }
            __syncthreads();
        }
    }

    if (tid < MAX_PER_IMG) {
        unsigned long long kk = skeys[tid];
        int r = (int)(kk & 0xFFFFFFFFull);
        float sc = __uint_as_float(~(uint32_t)(kk >> 32));
        int lbl2 = slabel[r];
        bool valid = sc > SCORE_THRESH;
        float4 bb = decode_box(rois, deltas, r, lbl2);

        if (out_size >= 5 * MAX_PER_IMG) {
            out[tid * 5 + 0] = valid ? sc : 0.0f;
            out[tid * 5 + 1] = valid ? bb.x : 0.0f;
            out[tid * 5 + 2] = valid ? bb.y : 0.0f;
            out[tid * 5 + 3] = valid ? bb.z : 0.0f;
            out[tid * 5 + 4] = valid ? bb.w : 0.0f;
        }
        if (out_size >= 6 * MAX_PER_IMG) out[5 * MAX_PER_IMG + tid] = (float)lbl2;
        if (out_size >= 7 * MAX_PER_IMG) out[6 * MAX_PER_IMG + tid] = (float)r;
    }
}

// ---------------------------------------------------------------------------
extern "C" void kernel_launch(void* const* d_in, const int* in_sizes, int n_in,
                              void* d_out, int out_size) {
    const float* rois   = (const float*)d_in[0];
    const float* deltas = (const float*)d_in[1];
    const float* scores = (const float*)d_in[2];
    float* out = (float*)d_out;

    fused_kernel<<<K, 512>>>(rois, deltas, scores, out, out_size);
}

// round 6
// speedup vs baseline: 4.4402x; 1.0874x over previous
#include <cuda_runtime.h>
#include <stdint.h>

#define R 512
#define K 81
#define IMW_M1 1332.0f
#define IMH_M1 799.0f
#define XCLIP 4.135166556742356f   // log(1000/16)
#define SCORE_THRESH 0.001f
#define POST_NMS_TOPN 300
#define MAX_PER_IMG 100
#define NT 1024

// scratch (no allocations allowed)
__device__ unsigned long long g_rmax[R];   // per-roi packed (score_bits<<32 | 255-class)
__device__ unsigned int g_sync;            // threadfence-reduction counter (self-reset)

// ---------------------------------------------------------------------------
// box decode for (roi r, class c), matching reference arithmetic order
// ---------------------------------------------------------------------------
__device__ __forceinline__ float4 decode_box(const float* __restrict__ rois,
                                             const float* __restrict__ deltas,
                                             int r, int c) {
    float4 roi = ((const float4*)rois)[r];
    float4 d = *(const float4*)(deltas + r * (4 * K) + c * 4);   // 16B aligned

    float w = roi.z - roi.x + 1.0f;
    float h = roi.w - roi.y + 1.0f;
    float cx = roi.x + 0.5f * w;
    float cy = roi.y + 0.5f * h;

    float dx = d.x / 10.0f;
    float dy = d.y / 10.0f;
    float dw = fminf(d.z / 5.0f, XCLIP);
    float dh = fminf(d.w / 5.0f, XCLIP);

    float pcx = dx * w + cx;
    float pcy = dy * h + cy;
    float pw = expf(dw) * w;
    float ph = expf(dh) * h;

    float4 o;
    o.x = fminf(fmaxf(pcx - 0.5f * pw, 0.0f), IMW_M1);
    o.y = fminf(fmaxf(pcy - 0.5f * ph, 0.0f), IMH_M1);
    o.z = fminf(fmaxf(pcx + 0.5f * pw - 1.0f, 0.0f), IMW_M1);
    o.w = fminf(fmaxf(pcy + 0.5f * ph - 1.0f, 0.0f), IMH_M1);
    return o;
}

// ---------------------------------------------------------------------------
// Fused kernel: decode + per-class NMS (one block/class) + last-block top-100.
// 1024 threads: 32 warps -> 8 warps/SMSP for latency hiding in the IoU loop.
// ---------------------------------------------------------------------------
__global__ void __launch_bounds__(NT, 1)
fused_kernel(const float* __restrict__ rois,
             const float* __restrict__ deltas,
             const float* __restrict__ scores,
             float* __restrict__ out, int out_size) {
    __shared__ unsigned long long skeys[R];     // (~score_bits)<<32 | idx (asc sort)
    __shared__ float4   sbox[R];
    __shared__ float    sarea[R];
    __shared__ uint32_t smask[R * 16];          // suppression bits, j>i only
    __shared__ uint32_t skeep[16];
    __shared__ int      sIsLast;

    const int c = blockIdx.x;
    const int tid = threadIdx.x;
    const int wid = tid >> 5;
    const int lane = tid & 31;

    // decode box (tid, c); stage by original index. sort key: desc score, asc idx.
    if (tid < R) {
        sbox[tid] = decode_box(rois, deltas, tid, c);
        float s = scores[tid * K + c];
        skeys[tid] = (((unsigned long long)(~__float_as_uint(s))) << 32) | (uint32_t)tid;
    }

    // zero suppression mask (1024 threads x 2 uint4)
    {
        uint4 z = make_uint4(0, 0, 0, 0);
        uint4* p = (uint4*)smask;
        p[tid] = z; p[tid + NT] = z;
    }
    __syncthreads();

    // shared-memory bitonic sort (ascending; unique keys => stable argsort)
    for (int k2 = 2; k2 <= R; k2 <<= 1) {
        for (int j = k2 >> 1; j > 0; j >>= 1) {
            int ixj = tid ^ j;
            if (tid < R && ixj > tid) {
                bool up = ((tid & k2) == 0);
                unsigned long long a = skeys[tid], b = skeys[ixj];
                if ((a > b) == up) { skeys[tid] = b; skeys[ixj] = a; }
            }
            __syncthreads();
        }
    }

    // permute boxes into sorted order; areas in reference expression order
    int orig = 0;
    float4 b4;
    if (tid < R) {
        orig = (int)(skeys[tid] & 0xFFFFFFFFull);
        b4 = sbox[orig];
    }
    __syncthreads();
    if (tid < R) {
        sbox[tid] = b4;
        sarea[tid] = (b4.z - b4.x + 1.0f) * (b4.w - b4.y + 1.0f);
    }
    __syncthreads();

    // ---- mask build: warp tiles (32 cols x 32 rows), ballot packing ----
    // 16 diagonal tiles first (w == rc), handled by warps 0..15 directly
    if (wid < 16) {
        int w = wid;
        int jcol = (w << 5) + lane;
        float4 cb = sbox[jcol];
        float ca = sarea[jcol];
        int i0 = w << 5;
        #pragma unroll 4
        for (int ii = 0; ii < 32; ii++) {
            int i = i0 + ii;
            float4 rb = sbox[i];
            float ra = sarea[i];
            float iw = fminf(cb.z, rb.z) - fmaxf(cb.x, rb.x) + 1.0f;
            float ih = fminf(cb.w, rb.w) - fmaxf(cb.y, rb.y) + 1.0f;
            float inter = fmaxf(iw, 0.0f) * fmaxf(ih, 0.0f);
            bool sup = (inter + inter > (ra + ca) - inter) && (jcol > i);
            uint32_t word = __ballot_sync(0xFFFFFFFFu, sup);
            if (lane == ii) smask[i * 16 + w] = word;
        }
    }
    // 120 strict upper-triangle tiles (rc < w), strided over all 32 warps
    for (int t = wid; t < 120; t += 32) {
        // map t -> (rc, w) with rc < w in 16x16 grid
        int rc = 0, tt = t;
        while (tt >= 15 - rc) { tt -= 15 - rc; rc++; }
        int w = rc + 1 + tt;

        int jcol = (w << 5) + lane;
        float4 cb = sbox[jcol];
        float ca = sarea[jcol];
        int i0 = rc << 5;
        #pragma unroll 4
        for (int ii = 0; ii < 32; ii++) {
            int i = i0 + ii;
            float4 rb = sbox[i];
            float ra = sarea[i];
            float iw = fminf(cb.z, rb.z) - fmaxf(cb.x, rb.x) + 1.0f;
            float ih = fminf(cb.w, rb.w) - fmaxf(cb.y, rb.y) + 1.0f;
            float inter = fmaxf(iw, 0.0f) * fmaxf(ih, 0.0f);
            bool sup = (inter + inter > (ra + ca) - inter);   // iou > 0.5
            uint32_t word = __ballot_sync(0xFFFFFFFFu, sup);
            if (lane == ii) smask[i * 16 + w] = word;
        }
    }
    __syncthreads();

    // ---- greedy suppression: warp 0, lane-replicated current word ----
    if (wid == 0) {
        uint32_t remw = 0;              // lane l (&15) owns removed word l&15
        const int lw = lane & 15;
        int kept = 0;
        #pragma unroll 1
        for (int ow = 0; ow < 16; ow++) {
            uint32_t cur = __shfl_sync(0xFFFFFFFFu, remw, ow);
            uint32_t mo[32];
            #pragma unroll
            for (int b = 0; b < 32; b++) mo[b] = smask[(ow * 32 + b) * 16 + ow];
            uint32_t kcur = 0;
            #pragma unroll
            for (int b = 0; b < 32; b++) {
                uint32_t ml = smask[(ow * 32 + b) * 16 + lw];
                if (!((cur >> b) & 1u)) {      // uniform: cur replicated in all lanes
                    kept++;
                    cur  |= mo[b];
                    remw |= ml;
                    if (kept <= POST_NMS_TOPN) kcur |= (1u << b);
                }
            }
            if (lane == 0) skeep[ow] = kcur;
        }
    }
    __syncthreads();

    // ---- per-roi class-max via packed atomicMax ----
    if (tid < R) {
        float topScore = __uint_as_float(~(uint32_t)(skeys[0] >> 32));
        bool cvalid = (c != 0) && (topScore > SCORE_THRESH);
        bool kp = (skeep[tid >> 5] >> (tid & 31)) & 1u;
        if (kp && cvalid) {
            uint32_t bits = ~(uint32_t)(skeys[tid] >> 32);   // score float bits (>0)
            unsigned long long key =
                (((unsigned long long)bits) << 32) | (unsigned int)(255 - c);
            atomicMax(&g_rmax[orig], key);
        }
    }

    // ---- threadfence reduction: last block runs the top-100 tail ----
    __threadfence();
    __syncthreads();
    if (tid == 0) {
        unsigned int done = atomicAdd(&g_sync, 1u);
        sIsLast = (done == K - 1) ? 1 : 0;
        if (done == K - 1) g_sync = 0;   // reset for next graph replay
    }
    __syncthreads();
    if (!sIsLast) return;

    // ================= tail: top-100 assembly =================
    int* slabel = (int*)smask;          // reuse shared

    // zero full output (poisoned by harness)
    for (int i = tid; i < out_size; i += NT) out[i] = 0.0f;

    // coherent read + self-reset in one atomic
    if (tid < R) {
        unsigned long long v = atomicExch(&g_rmax[tid], 0ull);
        uint32_t bits = (uint32_t)(v >> 32);            // 0 if nothing kept
        int lbl = (v != 0ull) ? (255 - (int)(v & 0xFFull)) : 0;
        slabel[tid] = lbl;
        skeys[tid] = (((unsigned long long)(~bits)) << 32) | (uint32_t)tid;
    }
    __syncthreads();

    // shared-memory bitonic sort (score desc, idx asc)
    for (int k2 = 2; k2 <= R; k2 <<= 1) {
        for (int j = k2 >> 1; j > 0; j >>= 1) {
            int ixj = tid ^ j;
            if (tid < R && ixj > tid) {
                bool up = ((tid & k2) == 0);
                unsigned long long a = skeys[tid], b = skeys[ixj];
                if ((a > b) == up) { skeys[tid] = b; skeys[ixj] = a; }
            }
            __syncthreads();
        }
    }

    if (tid < MAX_PER_IMG) {
        unsigned long long kk = skeys[tid];
        int r = (int)(kk & 0xFFFFFFFFull);
        float sc = __uint_as_float(~(uint32_t)(kk >> 32));
        int lbl2 = slabel[r];
        bool valid = sc > SCORE_THRESH;
        float4 bb = decode_box(rois, deltas, r, lbl2);

        if (out_size >= 5 * MAX_PER_IMG) {
            out[tid * 5 + 0] = valid ? sc : 0.0f;
            out[tid * 5 + 1] = valid ? bb.x : 0.0f;
            out[tid * 5 + 2] = valid ? bb.y : 0.0f;
            out[tid * 5 + 3] = valid ? bb.z : 0.0f;
            out[tid * 5 + 4] = valid ? bb.w : 0.0f;
        }
        if (out_size >= 6 * MAX_PER_IMG) out[5 * MAX_PER_IMG + tid] = (float)lbl2;
        if (out_size >= 7 * MAX_PER_IMG) out[6 * MAX_PER_IMG + tid] = (float)r;
    }
}

// ---------------------------------------------------------------------------
extern "C" void kernel_launch(void* const* d_in, const int* in_sizes, int n_in,
                              void* d_out, int out_size) {
    const float* rois   = (const float*)d_in[0];
    const float* deltas = (const float*)d_in[1];
    const float* scores = (const float*)d_in[2];
    float* out = (float*)d_out;

    fused_kernel<<<K, NT>>>(rois, deltas, scores, out, out_size);
}

// round 8
// speedup vs baseline: 4.7328x; 1.0659x over previous
#include <cuda_runtime.h>
#include <stdint.h>

#define R 512
#define K 81
#define IMW_M1 1332.0f
#define IMH_M1 799.0f
#define XCLIP 4.135166556742356f   // log(1000/16)
#define SCORE_THRESH 0.001f
#define POST_NMS_TOPN 300
#define MAX_PER_IMG 100
#define NT 1024

// scratch (no allocations allowed)
__device__ unsigned long long g_rmax[R];   // per-roi packed (score_bits<<32 | 255-class)
__device__ unsigned int g_sync;            // threadfence-reduction counter (self-reset)

// ---------------------------------------------------------------------------
// box decode for (roi r, class c), matching reference arithmetic order
// ---------------------------------------------------------------------------
__device__ __forceinline__ float4 decode_box(const float* __restrict__ rois,
                                             const float* __restrict__ deltas,
                                             int r, int c) {
    float4 roi = ((const float4*)rois)[r];
    float4 d = *(const float4*)(deltas + r * (4 * K) + c * 4);   // 16B aligned

    float w = roi.z - roi.x + 1.0f;
    float h = roi.w - roi.y + 1.0f;
    float cx = roi.x + 0.5f * w;
    float cy = roi.y + 0.5f * h;

    float dx = d.x / 10.0f;
    float dy = d.y / 10.0f;
    float dw = fminf(d.z / 5.0f, XCLIP);
    float dh = fminf(d.w / 5.0f, XCLIP);

    float pcx = dx * w + cx;
    float pcy = dy * h + cy;
    float pw = expf(dw) * w;
    float ph = expf(dh) * h;

    float4 o;
    o.x = fminf(fmaxf(pcx - 0.5f * pw, 0.0f), IMW_M1);
    o.y = fminf(fmaxf(pcy - 0.5f * ph, 0.0f), IMH_M1);
    o.z = fminf(fmaxf(pcx + 0.5f * pw - 1.0f, 0.0f), IMW_M1);
    o.w = fminf(fmaxf(pcy + 0.5f * ph - 1.0f, 0.0f), IMH_M1);
    return o;
}

// ---------------------------------------------------------------------------
// Hybrid bitonic sort of 512 u64 keys (ascending), 1 elem/thread, tid in [0,512).
// Intra-warp stages via shfl_xor (no barriers); 10 cross-warp steps via shared
// double-buffer with ONE named barrier (id 1, 512 threads) each.
// Buffers: bufA/bufB are 512-element regions (caller guarantees no other
// concurrent users). Returns the sorted element of rank tid.
// ---------------------------------------------------------------------------
__device__ __forceinline__ unsigned long long hybrid_sort512(
    unsigned long long key, int tid,
    unsigned long long* __restrict__ bufA,
    unsigned long long* __restrict__ bufB)
{
    const int lane = tid & 31;
    // k2 = 2..32: fully intra-warp
    #pragma unroll
    for (int k2 = 2; k2 <= 32; k2 <<= 1) {
        #pragma unroll
        for (int j = k2 >> 1; j > 0; j >>= 1) {
            bool up = ((tid & k2) == 0);
            bool amLow = ((lane & j) == 0);
            unsigned long long pk = __shfl_xor_sync(0xFFFFFFFFu, key, j);
            bool keepMin = (up == amLow);
            bool take = keepMin ? (pk < key) : (pk > key);
            if (take) key = pk;
        }
    }
    // k2 = 64..512: j>=32 cross-warp via shared, then j<32 intra-warp
    int par = 0;
    #pragma unroll
    for (int k2 = 64; k2 <= 512; k2 <<= 1) {
        bool up = ((tid & k2) == 0);
        #pragma unroll
        for (int j = k2 >> 1; j >= 32; j >>= 1) {
            unsigned long long* buf = par ? bufB : bufA;
            buf[tid] = key;
            asm volatile("bar.sync 1, 512;" ::: "memory");
            unsigned long long pk = buf[tid ^ j];
            bool amLow = ((tid & j) == 0);
            bool keepMin = (up == amLow);
            bool take = keepMin ? (pk < key) : (pk > key);
            if (take) key = pk;
            par ^= 1;
        }
        #pragma unroll
        for (int j = 16; j > 0; j >>= 1) {
            bool amLow = ((lane & j) == 0);
            unsigned long long pk = __shfl_xor_sync(0xFFFFFFFFu, key, j);
            bool keepMin = (up == amLow);
            bool take = keepMin ? (pk < key) : (pk > key);
            if (take) key = pk;
        }
    }
    return key;
}

// ---------------------------------------------------------------------------
// Fused kernel: decode + per-class NMS (one block/class) + last-block top-100.
// smem budget: smask 32K (first 8K doubles as sort scratch) + sbox 8K +
// sarea 2K (tail: labels) + misc  =  ~43.1 KB  (< 48 KB static limit).
// ---------------------------------------------------------------------------
__global__ void __launch_bounds__(NT, 1)
fused_kernel(const float* __restrict__ rois,
             const float* __restrict__ deltas,
             const float* __restrict__ scores,
             float* __restrict__ out, int out_size) {
    __shared__ uint32_t smask[R * 16];          // suppression bits; head = sort scratch
    __shared__ float4   sbox[R];
    __shared__ float    sarea[R];               // tail reuses as slabel
    __shared__ uint32_t skeep[16];
    __shared__ float    sTop;                   // class max score
    __shared__ int      sIsLast;

    unsigned long long* scratch = (unsigned long long*)smask;   // 1024 u64 capacity

    const int c = blockIdx.x;
    const int tid = threadIdx.x;
    const int wid = tid >> 5;
    const int lane = tid & 31;

    unsigned long long key = 0;   // sorted element of rank tid (warps 0-15)
    int orig = 0;

    if (wid < 16) {
        // sort key: descending score, ascending original index (softmax scores > 0)
        float s = scores[tid * K + c];
        key = (((unsigned long long)(~__float_as_uint(s))) << 32) | (uint32_t)tid;
        key = hybrid_sort512(key, tid, scratch, scratch + 512);
        orig = (int)(key & 0xFFFFFFFFull);
        if (tid == 0) sTop = __uint_as_float(~(uint32_t)(key >> 32));
    } else {
        // concurrently: decode boxes (disjoint from sort scratch)
        int t = tid - 512;
        sbox[t] = decode_box(rois, deltas, t, c);
    }
    __syncthreads();

    // read permuted box BEFORE zeroing/writing; zero smask with all threads
    float4 b4 = make_float4(0.f, 0.f, 0.f, 0.f);
    if (wid < 16) b4 = sbox[orig];
    {
        uint4 z = make_uint4(0, 0, 0, 0);
        uint4* p = (uint4*)smask;
        p[tid] = z; p[tid + NT] = z;
    }
    __syncthreads();
    if (wid < 16) {
        sbox[tid] = b4;
        sarea[tid] = (b4.z - b4.x + 1.0f) * (b4.w - b4.y + 1.0f);
    }
    __syncthreads();

    // ---- mask build: warp tiles (32 cols x 32 rows), ballot packing ----
    // 16 diagonal tiles (w == rc): warps 0..15
    if (wid < 16) {
        int w = wid;
        int jcol = (w << 5) + lane;
        float4 cb = sbox[jcol];
        float ca = sarea[jcol];
        int i0 = w << 5;
        #pragma unroll 4
        for (int ii = 0; ii < 32; ii++) {
            int i = i0 + ii;
            float4 rb = sbox[i];
            float ra = sarea[i];
            float iw = fminf(cb.z, rb.z) - fmaxf(cb.x, rb.x) + 1.0f;
            float ih = fminf(cb.w, rb.w) - fmaxf(cb.y, rb.y) + 1.0f;
            float inter = fmaxf(iw, 0.0f) * fmaxf(ih, 0.0f);
            bool sup = (inter + inter > (ra + ca) - inter) && (jcol > i);
            uint32_t word = __ballot_sync(0xFFFFFFFFu, sup);
            if (lane == ii) smask[i * 16 + w] = word;
        }
    }
    // 120 strict upper-triangle tiles (rc < w): all 32 warps
    for (int t = wid; t < 120; t += 32) {
        int rc = 0, tt = t;
        while (tt >= 15 - rc) { tt -= 15 - rc; rc++; }
        int w = rc + 1 + tt;

        int jcol = (w << 5) + lane;
        float4 cb = sbox[jcol];
        float ca = sarea[jcol];
        int i0 = rc << 5;
        #pragma unroll 4
        for (int ii = 0; ii < 32; ii++) {
            int i = i0 + ii;
            float4 rb = sbox[i];
            float ra = sarea[i];
            float iw = fminf(cb.z, rb.z) - fmaxf(cb.x, rb.x) + 1.0f;
            float ih = fminf(cb.w, rb.w) - fmaxf(cb.y, rb.y) + 1.0f;
            float inter = fmaxf(iw, 0.0f) * fmaxf(ih, 0.0f);
            bool sup = (inter + inter > (ra + ca) - inter);   // iou > 0.5
            uint32_t word = __ballot_sync(0xFFFFFFFFu, sup);
            if (lane == ii) smask[i * 16 + w] = word;
        }
    }
    __syncthreads();

    // ---- greedy suppression: warp 0, lane-replicated current word ----
    if (wid == 0) {
        uint32_t remw = 0;              // lane l (&15) owns removed word l&15
        const int lw = lane & 15;
        int kept = 0;
        #pragma unroll 1
        for (int ow = 0; ow < 16; ow++) {
            uint32_t cur = __shfl_sync(0xFFFFFFFFu, remw, ow);
            uint32_t mo[32];
            #pragma unroll
            for (int b = 0; b < 32; b++) mo[b] = smask[(ow * 32 + b) * 16 + ow];
            uint32_t kcur = 0;
            #pragma unroll
            for (int b = 0; b < 32; b++) {
                uint32_t ml = smask[(ow * 32 + b) * 16 + lw];
                if (!((cur >> b) & 1u)) {      // uniform: cur replicated in all lanes
                    kept++;
                    cur  |= mo[b];
                    remw |= ml;
                    if (kept <= POST_NMS_TOPN) kcur |= (1u << b);
                }
            }
            if (lane == 0) skeep[ow] = kcur;
        }
    }
    __syncthreads();

    // ---- per-roi class-max via packed atomicMax ----
    if (wid < 16) {
        bool cvalid = (c != 0) && (sTop > SCORE_THRESH);
        bool kp = (skeep[tid >> 5] >> (tid & 31)) & 1u;
        if (kp && cvalid) {
            uint32_t bits = ~(uint32_t)(key >> 32);   // score float bits (>0)
            unsigned long long pkey =
                (((unsigned long long)bits) << 32) | (unsigned int)(255 - c);
            atomicMax(&g_rmax[orig], pkey);
        }
    }

    // ---- threadfence reduction: last block runs the top-100 tail ----
    __threadfence();
    __syncthreads();
    if (tid == 0) {
        unsigned int done = atomicAdd(&g_sync, 1u);
        sIsLast = (done == K - 1) ? 1 : 0;
        if (done == K - 1) g_sync = 0;   // reset for next graph replay
    }
    __syncthreads();
    if (!sIsLast) return;

    // ================= tail: top-100 assembly =================
    int* slabel = (int*)sarea;          // reuse (areas dead)

    // zero full output (poisoned by harness)
    for (int i = tid; i < out_size; i += NT) out[i] = 0.0f;
    if (wid >= 16) return;              // warps 16-31 done

    // coherent read + self-reset in one atomic
    unsigned long long v = atomicExch(&g_rmax[tid], 0ull);
    uint32_t bits = (uint32_t)(v >> 32);            // 0 if nothing kept
    int lbl = (v != 0ull) ? (255 - (int)(v & 0xFFull)) : 0;
    slabel[tid] = lbl;
    unsigned long long tkey =
        (((unsigned long long)(~bits)) << 32) | (uint32_t)tid;

    // sort (scratch = smask head; NMS contents dead). Barriers inside also
    // publish slabel before the post-sort reads.
    tkey = hybrid_sort512(tkey, tid, scratch, scratch + 512);

    if (tid < MAX_PER_IMG) {
        int r = (int)(tkey & 0xFFFFFFFFull);
        float sc = __uint_as_float(~(uint32_t)(tkey >> 32));
        int lbl2 = slabel[r];
        bool valid = sc > SCORE_THRESH;
        float4 bb = decode_box(rois, deltas, r, lbl2);

        if (out_size >= 5 * MAX_PER_IMG) {
            out[tid * 5 + 0] = valid ? sc : 0.0f;
            out[tid * 5 + 1] = valid ? bb.x : 0.0f;
            out[tid * 5 + 2] = valid ? bb.y : 0.0f;
            out[tid * 5 + 3] = valid ? bb.z : 0.0f;
            out[tid * 5 + 4] = valid ? bb.w : 0.0f;
        }
        if (out_size >= 6 * MAX_PER_IMG) out[5 * MAX_PER_IMG + tid] = (float)lbl2;
        if (out_size >= 7 * MAX_PER_IMG) out[6 * MAX_PER_IMG + tid] = (float)r;
    }
}

// ---------------------------------------------------------------------------
extern "C" void kernel_launch(void* const* d_in, const int* in_sizes, int n_in,
                              void* d_out, int out_size) {
    const float* rois   = (const float*)d_in[0];
    const float* deltas = (const float*)d_in[1];
    const float* scores = (const float*)d_in[2];
    float* out = (float*)d_out;

    fused_kernel<<<K, NT>>>(rois, deltas, scores, out, out_size);
}

// round 9
// speedup vs baseline: 4.8724x; 1.0295x over previous
#include <cuda_runtime.h>
#include <stdint.h>

#define R 512
#define K 81
#define IMW_M1 1332.0f
#define IMH_M1 799.0f
#define XCLIP 4.135166556742356f   // log(1000/16)
#define SCORE_THRESH 0.001f
#define POST_NMS_TOPN 300
#define MAX_PER_IMG 100
#define NT 1024

// scratch (no allocations allowed)
__device__ unsigned long long g_rmax[R];   // per-roi packed (score_bits<<32 | 255-class)
__device__ unsigned int g_sync;            // threadfence-reduction counter (self-reset)

// ---------------------------------------------------------------------------
// box decode for (roi r, class c), matching reference arithmetic order
// ---------------------------------------------------------------------------
__device__ __forceinline__ float4 decode_box(const float* __restrict__ rois,
                                             const float* __restrict__ deltas,
                                             int r, int c) {
    float4 roi = ((const float4*)rois)[r];
    float4 d = *(const float4*)(deltas + r * (4 * K) + c * 4);   // 16B aligned

    float w = roi.z - roi.x + 1.0f;
    float h = roi.w - roi.y + 1.0f;
    float cx = roi.x + 0.5f * w;
    float cy = roi.y + 0.5f * h;

    float dx = d.x / 10.0f;
    float dy = d.y / 10.0f;
    float dw = fminf(d.z / 5.0f, XCLIP);
    float dh = fminf(d.w / 5.0f, XCLIP);

    float pcx = dx * w + cx;
    float pcy = dy * h + cy;
    float pw = expf(dw) * w;
    float ph = expf(dh) * h;

    float4 o;
    o.x = fminf(fmaxf(pcx - 0.5f * pw, 0.0f), IMW_M1);
    o.y = fminf(fmaxf(pcy - 0.5f * ph, 0.0f), IMH_M1);
    o.z = fminf(fmaxf(pcx + 0.5f * pw - 1.0f, 0.0f), IMW_M1);
    o.w = fminf(fmaxf(pcy + 0.5f * ph - 1.0f, 0.0f), IMH_M1);
    return o;
}

// ---------------------------------------------------------------------------
// Hybrid bitonic sort of 512 u64 keys (ascending), 1 elem/thread, tid in [0,512).
// Intra-warp via shfl_xor (no barriers); 10 cross-warp steps via shared
// double-buffer + one named barrier (id 1, 512 threads) each.
// ---------------------------------------------------------------------------
__device__ __forceinline__ unsigned long long hybrid_sort512(
    unsigned long long key, int tid,
    unsigned long long* __restrict__ bufA,
    unsigned long long* __restrict__ bufB)
{
    const int lane = tid & 31;
    #pragma unroll
    for (int k2 = 2; k2 <= 32; k2 <<= 1) {
        #pragma unroll
        for (int j = k2 >> 1; j > 0; j >>= 1) {
            bool up = ((tid & k2) == 0);
            bool amLow = ((lane & j) == 0);
            unsigned long long pk = __shfl_xor_sync(0xFFFFFFFFu, key, j);
            bool keepMin = (up == amLow);
            bool take = keepMin ? (pk < key) : (pk > key);
            if (take) key = pk;
        }
    }
    int par = 0;
    #pragma unroll
    for (int k2 = 64; k2 <= 512; k2 <<= 1) {
        bool up = ((tid & k2) == 0);
        #pragma unroll
        for (int j = k2 >> 1; j >= 32; j >>= 1) {
            unsigned long long* buf = par ? bufB : bufA;
            buf[tid] = key;
            asm volatile("bar.sync 1, 512;" ::: "memory");
            unsigned long long pk = buf[tid ^ j];
            bool amLow = ((tid & j) == 0);
            bool keepMin = (up == amLow);
            bool take = keepMin ? (pk < key) : (pk > key);
            if (take) key = pk;
            par ^= 1;
        }
        #pragma unroll
        for (int j = 16; j > 0; j >>= 1) {
            bool amLow = ((lane & j) == 0);
            unsigned long long pk = __shfl_xor_sync(0xFFFFFFFFu, key, j);
            bool keepMin = (up == amLow);
            bool take = keepMin ? (pk < key) : (pk > key);
            if (take) key = pk;
        }
    }
    return key;
}

// ---------------------------------------------------------------------------
// Fused kernel: decode + per-class NMS (one block/class) + last-block top-100.
// ---------------------------------------------------------------------------
__global__ void __launch_bounds__(NT, 1)
fused_kernel(const float* __restrict__ rois,
             const float* __restrict__ deltas,
             const float* __restrict__ scores,
             float* __restrict__ out, int out_size) {
    __shared__ uint32_t smask[R * 16];          // suppression bits; head = sort scratch
    __shared__ float4   sbox[R];                // sorted: (x1, y1, x2+1, y2+1)
    __shared__ float    sarea[R];               // tail reuses as slabel
    __shared__ uint32_t skeep[16];
    __shared__ float    sTop;                   // class max score
    __shared__ int      sIsLast;

    unsigned long long* scratch = (unsigned long long*)smask;   // 1024 u64 capacity

    const int c = blockIdx.x;
    const int tid = threadIdx.x;
    const int wid = tid >> 5;
    const int lane = tid & 31;

    unsigned long long key = 0;   // sorted element of rank tid (warps 0-15)
    int orig = 0;

    if (wid < 16) {
        // sort key: descending score, ascending original index (softmax scores > 0)
        float s = scores[tid * K + c];
        key = (((unsigned long long)(~__float_as_uint(s))) << 32) | (uint32_t)tid;
        key = hybrid_sort512(key, tid, scratch, scratch + 512);
        orig = (int)(key & 0xFFFFFFFFull);
        if (tid == 0) sTop = __uint_as_float(~(uint32_t)(key >> 32));
    } else {
        // concurrently: decode boxes (disjoint from sort scratch)
        int t = tid - 512;
        sbox[t] = decode_box(rois, deltas, t, c);
    }
    __syncthreads();

    // read permuted box BEFORE zeroing; zero smask with all 1024 threads
    float4 b4 = make_float4(0.f, 0.f, 0.f, 0.f);
    if (wid < 16) b4 = sbox[orig];
    {
        uint4 z = make_uint4(0, 0, 0, 0);
        uint4* p = (uint4*)smask;
        p[tid] = z; p[tid + NT] = z;
    }
    __syncthreads();
    if (wid < 16) {
        // area in reference expression order, then store pre-incremented coords
        sarea[tid] = (b4.z - b4.x + 1.0f) * (b4.w - b4.y + 1.0f);
        sbox[tid] = make_float4(b4.x, b4.y, b4.z + 1.0f, b4.w + 1.0f);
    }
    __syncthreads();

    // ---- mask build: warp tiles (32 cols x 32 rows), ballot packing ----
    // 16 diagonal tiles (w == rc): warps 0..15
    if (wid < 16) {
        int w = wid;
        int jcol = (w << 5) + lane;
        float4 cb = sbox[jcol];
        float ca = sarea[jcol];
        int i0 = w << 5;
        uint32_t* mp = smask + i0 * 16 + w;
        #pragma unroll 8
        for (int ii = 0; ii < 32; ii++) {
            int i = i0 + ii;
            float4 rb = sbox[i];
            float ra = sarea[i];
            float iw = fminf(cb.z, rb.z) - fmaxf(cb.x, rb.x);
            float ih = fminf(cb.w, rb.w) - fmaxf(cb.y, rb.y);
            float inter = fmaxf(iw, 0.0f) * fmaxf(ih, 0.0f);
            bool sup = (inter + inter > (ra + ca) - inter) && (jcol > i);
            uint32_t word = __ballot_sync(0xFFFFFFFFu, sup);
            if (lane == ii) *mp = word;
            mp += 16;
        }
    }
    // 120 strict upper-triangle tiles (rc < w): all 32 warps, closed-form map
    for (int t = wid; t < 120; t += 32) {
        // rc = largest with S(rc) = rc*(31-rc)/2 <= t
        float ft = (float)t;
        int rc = (int)((31.0f - sqrtf(961.0f - 8.0f * ft)) * 0.5f);
        // correction (float rounding safety)
        while (rc > 0 && t < (rc * (31 - rc)) / 2) rc--;
        while (t >= ((rc + 1) * (30 - rc)) / 2) rc++;
        int w = rc + 1 + (t - (rc * (31 - rc)) / 2);

        int jcol = (w << 5) + lane;
        float4 cb = sbox[jcol];
        float ca = sarea[jcol];
        int i0 = rc << 5;
        uint32_t* mp = smask + i0 * 16 + w;
        #pragma unroll 8
        for (int ii = 0; ii < 32; ii++) {
            float4 rb = sbox[i0 + ii];
            float ra = sarea[i0 + ii];
            float iw = fminf(cb.z, rb.z) - fmaxf(cb.x, rb.x);
            float ih = fminf(cb.w, rb.w) - fmaxf(cb.y, rb.y);
            float inter = fmaxf(iw, 0.0f) * fmaxf(ih, 0.0f);
            bool sup = (inter + inter > (ra + ca) - inter);   // iou > 0.5
            uint32_t word = __ballot_sync(0xFFFFFFFFu, sup);
            if (lane == ii) *mp = word;
            mp += 16;
        }
    }
    __syncthreads();

    // ---- greedy suppression: warp 0, lane-replicated current word ----
    if (wid == 0) {
        uint32_t remw = 0;              // lane l (&15) owns removed word l&15
        const int lw = lane & 15;
        int kept = 0;
        #pragma unroll 1
        for (int ow = 0; ow < 16; ow++) {
            uint32_t cur = __shfl_sync(0xFFFFFFFFu, remw, ow);
            uint32_t mo[32];
            #pragma unroll
            for (int b = 0; b < 32; b++) mo[b] = smask[(ow * 32 + b) * 16 + ow];
            uint32_t kcur = 0;
            #pragma unroll
            for (int b = 0; b < 32; b++) {
                uint32_t ml = smask[(ow * 32 + b) * 16 + lw];
                if (!((cur >> b) & 1u)) {      // uniform: cur replicated in all lanes
                    kept++;
                    cur  |= mo[b];
                    remw |= ml;
                    if (kept <= POST_NMS_TOPN) kcur |= (1u << b);
                }
            }
            if (lane == 0) skeep[ow] = kcur;
        }
    }
    __syncthreads();

    // ---- per-roi class-max via packed atomicMax ----
    if (wid < 16) {
        bool cvalid = (c != 0) && (sTop > SCORE_THRESH);
        bool kp = (skeep[tid >> 5] >> (tid & 31)) & 1u;
        if (kp && cvalid) {
            uint32_t bits = ~(uint32_t)(key >> 32);   // score float bits (>0)
            unsigned long long pkey =
                (((unsigned long long)bits) << 32) | (unsigned int)(255 - c);
            atomicMax(&g_rmax[orig], pkey);
        }
    }

    // ---- threadfence reduction: last block runs the top-100 tail ----
    __threadfence();
    __syncthreads();
    if (tid == 0) {
        unsigned int done = atomicAdd(&g_sync, 1u);
        sIsLast = (done == K - 1) ? 1 : 0;
        if (done == K - 1) g_sync = 0;   // reset for next graph replay
    }
    __syncthreads();
    if (!sIsLast) return;

    // ================= tail: top-100 assembly =================
    int* slabel = (int*)sarea;          // reuse (areas dead)

    // zero full output (poisoned by harness)
    for (int i = tid; i < out_size; i += NT) out[i] = 0.0f;
    if (wid >= 16) return;              // warps 16-31 done

    // coherent read + self-reset in one atomic
    unsigned long long v = atomicExch(&g_rmax[tid], 0ull);
    uint32_t bits = (uint32_t)(v >> 32);            // 0 if nothing kept
    int lbl = (v != 0ull) ? (255 - (int)(v & 0xFFull)) : 0;
    slabel[tid] = lbl;
    unsigned long long tkey =
        (((unsigned long long)(~bits)) << 32) | (uint32_t)tid;

    // sort (scratch = smask head; NMS contents dead). Barriers inside also
    // publish slabel before the post-sort reads.
    tkey = hybrid_sort512(tkey, tid, scratch, scratch + 512);

    if (tid < MAX_PER_IMG) {
        int r = (int)(tkey & 0xFFFFFFFFull);
        float sc = __uint_as_float(~(uint32_t)(tkey >> 32));
        int lbl2 = slabel[r];
        bool valid = sc > SCORE_THRESH;
        float4 bb = decode_box(rois, deltas, r, lbl2);

        if (out_size >= 5 * MAX_PER_IMG) {
            out[tid * 5 + 0] = valid ? sc : 0.0f;
            out[tid * 5 + 1] = valid ? bb.x : 0.0f;
            out[tid * 5 + 2] = valid ? bb.y : 0.0f;
            out[tid * 5 + 3] = valid ? bb.z : 0.0f;
            out[tid * 5 + 4] = valid ? bb.w : 0.0f;
        }
        if (out_size >= 6 * MAX_PER_IMG) out[5 * MAX_PER_IMG + tid] = (float)lbl2;
        if (out_size >= 7 * MAX_PER_IMG) out[6 * MAX_PER_IMG + tid] = (float)r;
    }
}

// ---------------------------------------------------------------------------
extern "C" void kernel_launch(void* const* d_in, const int* in_sizes, int n_in,
                              void* d_out, int out_size) {
    const float* rois   = (const float*)d_in[0];
    const float* deltas = (const float*)d_in[1];
    const float* scores = (const float*)d_in[2];
    float* out = (float*)d_out;

    fused_kernel<<<K, NT>>>(rois, deltas, scores, out, out_size);
}

// round 10
// speedup vs baseline: 4.9864x; 1.0234x over previous
#include <cuda_runtime.h>
#include <stdint.h>

#define R 512
#define K 81
#define IMW_M1 1332.0f
#define IMH_M1 799.0f
#define XCLIP 4.135166556742356f   // log(1000/16)
#define SCORE_THRESH 0.001f
#define POST_NMS_TOPN 300
#define MAX_PER_IMG 100
#define NT 1024

// scratch (no allocations allowed)
__device__ unsigned long long g_rmax[R];   // per-roi packed (score_bits<<32 | 255-class)
__device__ unsigned int g_sync;            // threadfence-reduction counter (self-reset)

// ---------------------------------------------------------------------------
// box decode for (roi r, class c), matching reference arithmetic order
// ---------------------------------------------------------------------------
__device__ __forceinline__ float4 decode_box(const float* __restrict__ rois,
                                             const float* __restrict__ deltas,
                                             int r, int c) {
    float4 roi = ((const float4*)rois)[r];
    float4 d = *(const float4*)(deltas + r * (4 * K) + c * 4);   // 16B aligned

    float w = roi.z - roi.x + 1.0f;
    float h = roi.w - roi.y + 1.0f;
    float cx = roi.x + 0.5f * w;
    float cy = roi.y + 0.5f * h;

    float dx = d.x / 10.0f;
    float dy = d.y / 10.0f;
    float dw = fminf(d.z / 5.0f, XCLIP);
    float dh = fminf(d.w / 5.0f, XCLIP);

    float pcx = dx * w + cx;
    float pcy = dy * h + cy;
    float pw = expf(dw) * w;
    float ph = expf(dh) * h;

    float4 o;
    o.x = fminf(fmaxf(pcx - 0.5f * pw, 0.0f), IMW_M1);
    o.y = fminf(fmaxf(pcy - 0.5f * ph, 0.0f), IMH_M1);
    o.z = fminf(fmaxf(pcx + 0.5f * pw - 1.0f, 0.0f), IMW_M1);
    o.w = fminf(fmaxf(pcy + 0.5f * ph - 1.0f, 0.0f), IMH_M1);
    return o;
}

// ---------------------------------------------------------------------------
// Hybrid bitonic sort of 512 u64 keys (ascending), 1 elem/thread, tid in [0,512).
// Intra-warp via shfl_xor (no barriers); 10 cross-warp steps via shared
// double-buffer + one named barrier (id 1, 512 threads) each.
// ---------------------------------------------------------------------------
__device__ __forceinline__ unsigned long long hybrid_sort512(
    unsigned long long key, int tid,
    unsigned long long* __restrict__ bufA,
    unsigned long long* __restrict__ bufB)
{
    const int lane = tid & 31;
    #pragma unroll
    for (int k2 = 2; k2 <= 32; k2 <<= 1) {
        #pragma unroll
        for (int j = k2 >> 1; j > 0; j >>= 1) {
            bool up = ((tid & k2) == 0);
            bool amLow = ((lane & j) == 0);
            unsigned long long pk = __shfl_xor_sync(0xFFFFFFFFu, key, j);
            bool keepMin = (up == amLow);
            bool take = keepMin ? (pk < key) : (pk > key);
            if (take) key = pk;
        }
    }
    int par = 0;
    #pragma unroll
    for (int k2 = 64; k2 <= 512; k2 <<= 1) {
        bool up = ((tid & k2) == 0);
        #pragma unroll
        for (int j = k2 >> 1; j >= 32; j >>= 1) {
            unsigned long long* buf = par ? bufB : bufA;
            buf[tid] = key;
            asm volatile("bar.sync 1, 512;" ::: "memory");
            unsigned long long pk = buf[tid ^ j];
            bool amLow = ((tid & j) == 0);
            bool keepMin = (up == amLow);
            bool take = keepMin ? (pk < key) : (pk > key);
            if (take) key = pk;
            par ^= 1;
        }
        #pragma unroll
        for (int j = 16; j > 0; j >>= 1) {
            bool amLow = ((lane & j) == 0);
            unsigned long long pk = __shfl_xor_sync(0xFFFFFFFFu, key, j);
            bool keepMin = (up == amLow);
            bool take = keepMin ? (pk < key) : (pk > key);
            if (take) key = pk;
        }
    }
    return key;
}

// ---------------------------------------------------------------------------
// Fused kernel: decode + per-class NMS (one block/class) + last-block top-100.
// ---------------------------------------------------------------------------
__global__ void __launch_bounds__(NT, 1)
fused_kernel(const float* __restrict__ rois,
             const float* __restrict__ deltas,
             const float* __restrict__ scores,
             float* __restrict__ out, int out_size) {
    __shared__ uint32_t smask[R * 16];          // suppression bits; head = sort scratch
    __shared__ float4   sbox[R];                // sorted: (x1, y1, x2+1, y2+1)
    __shared__ float    sarea[R];               // tail reuses as slabel
    __shared__ uint32_t skeep[16];
    __shared__ float    sTop;                   // class max score
    __shared__ int      sIsLast;

    unsigned long long* scratch = (unsigned long long*)smask;   // 1024 u64 capacity

    const int c = blockIdx.x;
    const int tid = threadIdx.x;
    const int wid = tid >> 5;
    const int lane = tid & 31;

    unsigned long long key = 0;   // sorted element of rank tid (warps 0-15)
    int orig = 0;

    if (wid < 16) {
        // sort key: descending score, ascending original index (softmax scores > 0)
        float s = scores[tid * K + c];
        key = (((unsigned long long)(~__float_as_uint(s))) << 32) | (uint32_t)tid;
        key = hybrid_sort512(key, tid, scratch, scratch + 512);
        orig = (int)(key & 0xFFFFFFFFull);
        if (tid == 0) sTop = __uint_as_float(~(uint32_t)(key >> 32));
    } else {
        // concurrently: decode boxes (disjoint from sort scratch)
        int t = tid - 512;
        sbox[t] = decode_box(rois, deltas, t, c);
    }
    __syncthreads();

    // read permuted box BEFORE zeroing; zero smask with all 1024 threads
    float4 b4 = make_float4(0.f, 0.f, 0.f, 0.f);
    if (wid < 16) b4 = sbox[orig];
    {
        uint4 z = make_uint4(0, 0, 0, 0);
        uint4* p = (uint4*)smask;
        p[tid] = z; p[tid + NT] = z;
    }
    __syncthreads();
    if (wid < 16) {
        // area in reference expression order, then store pre-incremented coords
        sarea[tid] = (b4.z - b4.x + 1.0f) * (b4.w - b4.y + 1.0f);
        sbox[tid] = make_float4(b4.x, b4.y, b4.z + 1.0f, b4.w + 1.0f);
    }
    __syncthreads();

    // ---- mask build: tiles of 32 rows x 64 cols (2 col boxes per lane) ----
    // iou > 0.5  <=>  3*inter > ra+ca  <=>  fmaf(3, inter, -ca) > ra
    //
    // Diagonal coverage (warps 0-15): warp w handles rows [32w,32w+32):
    //   word w (diagonal, needs jcol>i); even w additionally word w+1 (full).
    if (wid < 16) {
        int w = wid;
        int i0 = w << 5;
        int j0 = (w << 5) + lane;
        float4 cb0 = sbox[j0];
        float nca0 = -sarea[j0];
        bool hasW1 = ((w & 1) == 0);
        float4 cb1 = cb0; float nca1 = nca0;
        if (hasW1) { cb1 = sbox[j0 + 32]; nca1 = -sarea[j0 + 32]; }
        uint32_t* mp = smask + i0 * 16 + w;
        #pragma unroll 8
        for (int ii = 0; ii < 32; ii++) {
            int i = i0 + ii;
            float4 rb = sbox[i];
            float ra = sarea[i];
            float iw0 = fminf(cb0.z, rb.z) - fmaxf(cb0.x, rb.x);
            float ih0 = fminf(cb0.w, rb.w) - fmaxf(cb0.y, rb.y);
            float in0 = fmaxf(iw0, 0.0f) * fmaxf(ih0, 0.0f);
            bool sup0 = (fmaf(3.0f, in0, nca0) > ra) && (j0 > i);
            uint32_t w0 = __ballot_sync(0xFFFFFFFFu, sup0);
            float iw1 = fminf(cb1.z, rb.z) - fmaxf(cb1.x, rb.x);
            float ih1 = fminf(cb1.w, rb.w) - fmaxf(cb1.y, rb.y);
            float in1 = fmaxf(iw1, 0.0f) * fmaxf(ih1, 0.0f);
            bool sup1 = hasW1 && (fmaf(3.0f, in1, nca1) > ra);
            uint32_t w1 = __ballot_sync(0xFFFFFFFFu, sup1);
            if (lane == ii) { mp[0] = w0; if (hasW1) mp[1] = w1; }
            mp += 16;
        }
    }

    // Full 64-col tiles: (cc, rc) with rc < 2*cc, cc in 1..7 -> 56 tiles.
    // Balanced schedule (word-chunk load): warps 16-31: 2 tiles; odd warps
    // 1..15: 2 tiles; even warps 0..14: 1 tile.  Max load = 5 chunks.
    {
        int nfull, tbase;
        if (wid >= 16)      { nfull = 2; tbase = (wid - 16) * 2; }
        else if (wid & 1)   { nfull = 2; tbase = 32 + (wid >> 1) * 2; }
        else                { nfull = 1; tbase = 48 + (wid >> 1); }

        for (int q = 0; q < nfull; q++) {
            int t = tbase + q;
            // cc = floor((1+sqrt(1+4t))/2); rc = t - cc*(cc-1)
            int cc = (int)((1.0f + sqrtf(1.0f + 4.0f * (float)t)) * 0.5f);
            while (t < cc * (cc - 1)) cc--;
            while (t >= cc * (cc + 1)) cc++;
            int rc = t - cc * (cc - 1);

            int j0 = (cc << 6) + lane;
            float4 cb0 = sbox[j0];
            float4 cb1 = sbox[j0 + 32];
            float nca0 = -sarea[j0];
            float nca1 = -sarea[j0 + 32];
            int i0 = rc << 5;
            uint32_t* mp = smask + i0 * 16 + (cc << 1);
            #pragma unroll 8
            for (int ii = 0; ii < 32; ii++) {
                float4 rb = sbox[i0 + ii];
                float ra = sarea[i0 + ii];
                float iw0 = fminf(cb0.z, rb.z) - fmaxf(cb0.x, rb.x);
                float ih0 = fminf(cb0.w, rb.w) - fmaxf(cb0.y, rb.y);
                float in0 = fmaxf(iw0, 0.0f) * fmaxf(ih0, 0.0f);
                bool sup0 = (fmaf(3.0f, in0, nca0) > ra);
                uint32_t w0 = __ballot_sync(0xFFFFFFFFu, sup0);
                float iw1 = fminf(cb1.z, rb.z) - fmaxf(cb1.x, rb.x);
                float ih1 = fminf(cb1.w, rb.w) - fmaxf(cb1.y, rb.y);
                float in1 = fmaxf(iw1, 0.0f) * fmaxf(ih1, 0.0f);
                bool sup1 = (fmaf(3.0f, in1, nca1) > ra);
                uint32_t w1 = __ballot_sync(0xFFFFFFFFu, sup1);
                if (lane == ii) { mp[0] = w0; mp[1] = w1; }
                mp += 16;
            }
        }
    }
    __syncthreads();

    // ---- greedy suppression: warp 0, lane-replicated current word ----
    if (wid == 0) {
        uint32_t remw = 0;              // lane l (&15) owns removed word l&15
        const int lw = lane & 15;
        int kept = 0;
        #pragma unroll 1
        for (int ow = 0; ow < 16; ow++) {
            uint32_t cur = __shfl_sync(0xFFFFFFFFu, remw, ow);
            uint32_t mo[32];
            #pragma unroll
            for (int b = 0; b < 32; b++) mo[b] = smask[(ow * 32 + b) * 16 + ow];
            uint32_t kcur = 0;
            #pragma unroll
            for (int b = 0; b < 32; b++) {
                uint32_t ml = smask[(ow * 32 + b) * 16 + lw];
                if (!((cur >> b) & 1u)) {      // uniform: cur replicated in all lanes
                    kept++;
                    cur  |= mo[b];
                    remw |= ml;
                    if (kept <= POST_NMS_TOPN) kcur |= (1u << b);
                }
            }
            if (lane == 0) skeep[ow] = kcur;
        }
    }
    __syncthreads();

    // ---- per-roi class-max via packed atomicMax ----
    if (wid < 16) {
        bool cvalid = (c != 0) && (sTop > SCORE_THRESH);
        bool kp = (skeep[tid >> 5] >> (tid & 31)) & 1u;
        if (kp && cvalid) {
            uint32_t bits = ~(uint32_t)(key >> 32);   // score float bits (>0)
            unsigned long long pkey =
                (((unsigned long long)bits) << 32) | (unsigned int)(255 - c);
            atomicMax(&g_rmax[orig], pkey);
        }
    }

    // ---- threadfence reduction: last block runs the top-100 tail ----
    __threadfence();
    __syncthreads();
    if (tid == 0) {
        unsigned int done = atomicAdd(&g_sync, 1u);
        sIsLast = (done == K - 1) ? 1 : 0;
        if (done == K - 1) g_sync = 0;   // reset for next graph replay
    }
    __syncthreads();
    if (!sIsLast) return;

    // ================= tail: top-100 assembly =================
    int* slabel = (int*)sarea;          // reuse (areas dead)

    // zero full output (poisoned by harness)
    for (int i = tid; i < out_size; i += NT) out[i] = 0.0f;
    if (wid >= 16) return;              // warps 16-31 done

    // coherent read + self-reset in one atomic
    unsigned long long v = atomicExch(&g_rmax[tid], 0ull);
    uint32_t bits = (uint32_t)(v >> 32);            // 0 if nothing kept
    int lbl = (v != 0ull) ? (255 - (int)(v & 0xFFull)) : 0;
    slabel[tid] = lbl;
    unsigned long long tkey =
        (((unsigned long long)(~bits)) << 32) | (uint32_t)tid;

    // sort (scratch = smask head; NMS contents dead). Barriers inside also
    // publish slabel before the post-sort reads.
    tkey = hybrid_sort512(tkey, tid, scratch, scratch + 512);

    if (tid < MAX_PER_IMG) {
        int r = (int)(tkey & 0xFFFFFFFFull);
        float sc = __uint_as_float(~(uint32_t)(tkey >> 32));
        int lbl2 = slabel[r];
        bool valid = sc > SCORE_THRESH;
        float4 bb = decode_box(rois, deltas, r, lbl2);

        if (out_size >= 5 * MAX_PER_IMG) {
            out[tid * 5 + 0] = valid ? sc : 0.0f;
            out[tid * 5 + 1] = valid ? bb.x : 0.0f;
            out[tid * 5 + 2] = valid ? bb.y : 0.0f;
            out[tid * 5 + 3] = valid ? bb.z : 0.0f;
            out[tid * 5 + 4] = valid ? bb.w : 0.0f;
        }
        if (out_size >= 6 * MAX_PER_IMG) out[5 * MAX_PER_IMG + tid] = (float)lbl2;
        if (out_size >= 7 * MAX_PER_IMG) out[6 * MAX_PER_IMG + tid] = (float)r;
    }
}

// ---------------------------------------------------------------------------
extern "C" void kernel_launch(void* const* d_in, const int* in_sizes, int n_in,
                              void* d_out, int out_size) {
    const float* rois   = (const float*)d_in[0];
    const float* deltas = (const float*)d_in[1];
    const float* scores = (const float*)d_in[2];
    float* out = (float*)d_out;

    fused_kernel<<<K, NT>>>(rois, deltas, scores, out, out_size);
}